// round 14
// baseline (speedup 1.0000x reference)
#include <cuda_runtime.h>
#include <math.h>

#define VOCAB 32000
#define BATCH 64
#define FRAME 4096
#define HID 256
#define VSTEP 80
#define CSTEP 50
#define TSTEPS (VSTEP + CSTEP - 1)
#define DEC (CSTEP - 1)
#define BH (BATCH * HID)
#define NBLK_ENC 128
#define ENC_ITERS 130

__device__ float g_v  [VSTEP * BATCH * HID];
__device__ float g_xg1[VSTEP * BATCH * 4 * HID];
__device__ float g_xg2[VSTEP * BATCH * 4 * HID];   // reused as xgd
__device__ float g_vid[(TSTEPS + 1) * BATCH * HID];
__device__ float g_c2 [BH];
__device__ float g_h2 [2 * BH];
__device__ float g_bs1[4 * HID];
__device__ float g_bs2[4 * HID];
__device__ float g_w2t[HID * VOCAB];               // w2 transposed [k][n]
__device__ unsigned long long g_gmax[2][BATCH];
__device__ int g_bar_sense;
__device__ unsigned g_bar_count;

__device__ __forceinline__ unsigned f2ord(float f) {
    unsigned u = __float_as_uint(f);
    return (u & 0x80000000u) ? ~u : (u | 0x80000000u);
}
__device__ __forceinline__ float sigm(float x) { return 1.f / (1.f + expf(-x)); }
__device__ __forceinline__ int dec_tok(unsigned long long p) {
    return (int)(0xFFFFFFFFu - (unsigned)(p & 0xFFFFFFFFull));
}
__device__ __forceinline__ unsigned long long pkmax(unsigned long long a, unsigned long long b) {
    return a > b ? a : b;
}

__global__ void k_zero() {
    int i = blockIdx.x * blockDim.x + threadIdx.x;
    if (i < BH) { g_h2[i] = 0.f; g_h2[BH + i] = 0.f; }
}
__global__ void k_bias(const float* a1, const float* b1, const float* a2, const float* b2) {
    int i = blockIdx.x * 256 + threadIdx.x;
    if (i < 4 * HID) { g_bs1[i] = a1[i] + b1[i]; g_bs2[i] = a2[i] + b2[i]; }
}

// transpose w2 [n][k] -> g_w2t [k][n]
__global__ __launch_bounds__(256) void k_tr(const float* __restrict__ w2) {
    __shared__ float tile[32][33];
    int bx = blockIdx.x, by = blockIdx.y;
    int x = threadIdx.x & 31, y = threadIdx.x >> 5;
#pragma unroll
    for (int j = 0; j < 4; j++)
        tile[y + j * 8][x] = w2[(size_t)(bx * 32 + y + j * 8) * HID + by * 32 + x];
    __syncthreads();
#pragma unroll
    for (int j = 0; j < 4; j++) {
        int kk = y + j * 8;
        g_w2t[(size_t)(by * 32 + kk) * VOCAB + bx * 32 + x] = tile[x][kk];
    }
}

// 128x64 tile GEMM (K=256 hoists)
__global__ __launch_bounds__(256) void k_gemm(
    const float* __restrict__ A, int lda,
    const float* __restrict__ W, int ldw, int wcol,
    const float* __restrict__ bias,
    float* __restrict__ C, int ldc, int K, int permT)
{
    __shared__ float As[16][132];
    __shared__ float Bs[16][68];
    int tid = threadIdx.x, tx = tid & 15, ty = tid >> 4;
    int m0 = blockIdx.x * 128, n0 = blockIdx.y * 64;
    float4 acc[8];
#pragma unroll
    for (int i = 0; i < 8; i++) acc[i] = make_float4(0.f,0.f,0.f,0.f);
    for (int k0 = 0; k0 < K; k0 += 16) {
#pragma unroll
        for (int i = 0; i < 2; i++) {
            int idx = tid + i * 256, r = idx >> 2, kq = (idx & 3) << 2;
            float4 va = *(const float4*)(A + (size_t)(m0 + r) * lda + k0 + kq);
            As[kq][r]=va.x; As[kq+1][r]=va.y; As[kq+2][r]=va.z; As[kq+3][r]=va.w;
        }
        {
            int r = tid >> 2, kq = (tid & 3) << 2;
            float4 vb = *(const float4*)(W + (size_t)(n0 + r) * ldw + wcol + k0 + kq);
            Bs[kq][r]=vb.x; Bs[kq+1][r]=vb.y; Bs[kq+2][r]=vb.z; Bs[kq+3][r]=vb.w;
        }
        __syncthreads();
#pragma unroll
        for (int k = 0; k < 16; k++) {
            float4 b4 = *(const float4*)&Bs[k][tx * 4];
            float4 a0 = *(const float4*)&As[k][ty * 8];
            float4 a1 = *(const float4*)&As[k][ty * 8 + 4];
            float av[8] = {a0.x,a0.y,a0.z,a0.w,a1.x,a1.y,a1.z,a1.w};
#pragma unroll
            for (int i = 0; i < 8; i++) {
                acc[i].x = fmaf(av[i], b4.x, acc[i].x);
                acc[i].y = fmaf(av[i], b4.y, acc[i].y);
                acc[i].z = fmaf(av[i], b4.z, acc[i].z);
                acc[i].w = fmaf(av[i], b4.w, acc[i].w);
            }
        }
        __syncthreads();
    }
    float4 bb = *(const float4*)(bias + n0 + tx * 4);
#pragma unroll
    for (int i = 0; i < 8; i++) {
        int m = m0 + ty * 8 + i;
        int orow = permT ? ((m % permT) * BATCH + m / permT) : m;
        *(float4*)(C + (size_t)orow * ldc + n0 + tx * 4) =
            make_float4(acc[i].x+bb.x, acc[i].y+bb.y, acc[i].z+bb.z, acc[i].w+bb.w);
    }
}

// 64x64 tile GEMM for the big-K video projection
__global__ __launch_bounds__(256) void k_gemm64(
    const float* __restrict__ A, int lda,
    const float* __restrict__ W, int ldw,
    const float* __restrict__ bias,
    float* __restrict__ C, int ldc, int K, int permT)
{
    __shared__ float As[16][68];
    __shared__ float Bs[16][68];
    int tid = threadIdx.x, tx = tid & 15, ty = tid >> 4;
    int m0 = blockIdx.x * 64, n0 = blockIdx.y * 64;
    float4 acc[4];
#pragma unroll
    for (int i = 0; i < 4; i++) acc[i] = make_float4(0.f,0.f,0.f,0.f);
    for (int k0 = 0; k0 < K; k0 += 16) {
        {
            int r = tid >> 2, kq = (tid & 3) << 2;
            float4 va = *(const float4*)(A + (size_t)(m0 + r) * lda + k0 + kq);
            As[kq][r]=va.x; As[kq+1][r]=va.y; As[kq+2][r]=va.z; As[kq+3][r]=va.w;
            float4 vb = *(const float4*)(W + (size_t)(n0 + r) * ldw + k0 + kq);
            Bs[kq][r]=vb.x; Bs[kq+1][r]=vb.y; Bs[kq+2][r]=vb.z; Bs[kq+3][r]=vb.w;
        }
        __syncthreads();
#pragma unroll
        for (int k = 0; k < 16; k++) {
            float4 b4 = *(const float4*)&Bs[k][tx * 4];
            float4 a4 = *(const float4*)&As[k][ty * 4];
            float av[4] = {a4.x, a4.y, a4.z, a4.w};
#pragma unroll
            for (int i = 0; i < 4; i++) {
                acc[i].x = fmaf(av[i], b4.x, acc[i].x);
                acc[i].y = fmaf(av[i], b4.y, acc[i].y);
                acc[i].z = fmaf(av[i], b4.z, acc[i].z);
                acc[i].w = fmaf(av[i], b4.w, acc[i].w);
            }
        }
        __syncthreads();
    }
    float4 bb = *(const float4*)(bias + n0 + tx * 4);
#pragma unroll
    for (int i = 0; i < 4; i++) {
        int m = m0 + ty * 4 + i;
        int orow = permT ? ((m % permT) * BATCH + m / permT) : m;
        *(float4*)(C + (size_t)orow * ldc + n0 + tx * 4) =
            make_float4(acc[i].x+bb.x, acc[i].y+bb.y, acc[i].z+bb.z, acc[i].w+bb.w);
    }
}

// ---- persistent fused encoder: blocks 0..63 = LSTM1, 64..127 = LSTM2-enc ----
#define WROW 260
__global__ __launch_bounds__(256) void k_enc(
    const float* __restrict__ l1_whh, const float* __restrict__ l2_wih,
    const float* __restrict__ l2_whh)
{
    extern __shared__ float sm[];
    float* w0 = sm;
    float* w1 = sm + 4 * 16 * WROW;
    float* xs = sm + 2 * 4 * 16 * WROW;

    int tid = threadIdx.x, bl = tid & 15, cl = tid >> 4;
    int bid = blockIdx.x;
    int role = bid >> 6;
    int lb = bid & 63, ct = lb & 15, bt = lb >> 4;
    int b = bt * 16 + bl, c = ct * 16 + cl;

    for (int i = tid; i < 4096; i += 256) {
        int row = i >> 6, kq = (i & 63) << 2;
        int g = row >> 4, cr = row & 15;
        int wrow = g * 256 + ct * 16 + cr;
        float* dst = w0 + (g * 16 + cr) * WROW + kq;
        if (role == 0) {
            float4 v = *(const float4*)(l1_whh + (size_t)wrow * 256 + kq);
            dst[0]=v.x; dst[1]=v.y; dst[2]=v.z; dst[3]=v.w;
        } else {
            float4 v = *(const float4*)(l2_wih + (size_t)wrow * 512 + 256 + kq);
            dst[0]=v.x; dst[1]=v.y; dst[2]=v.z; dst[3]=v.w;
            float4 u = *(const float4*)(l2_whh + (size_t)wrow * 256 + kq);
            float* d2 = w1 + (g * 16 + cr) * WROW + kq;
            d2[0]=u.x; d2[1]=u.y; d2[2]=u.z; d2[3]=u.w;
        }
    }

    float c_reg = 0.f;
    int sense = 0;
    volatile int* vsense = &g_bar_sense;

    for (int s = 0; s < ENC_ITERS; s++) {
        __syncthreads();
        if (tid == 0) {
            __threadfence();
            sense ^= 1;
            unsigned old = atomicAdd(&g_bar_count, 1u);
            if (old == (unsigned)(NBLK_ENC - 1)) {
                g_bar_count = 0u;
                __threadfence();
                *vsense = sense;
            } else {
                while (*vsense != sense) __nanosleep(64);
                __threadfence();
            }
        }
        __syncthreads();

        if (role == 0) {
            if (s < TSTEPS) {
                int t = s;
                {
                    int r = tid >> 4, k16 = (tid & 15) << 4;
                    const float* hp = (t == 0) ? (const float*)0
                        : g_vid + (size_t)(t - 1) * BH + (bt * 16 + r) * HID;
#pragma unroll
                    for (int q = 0; q < 4; q++) {
                        float4 v = hp ? *(const float4*)(hp + k16 + q * 4)
                                      : make_float4(0.f,0.f,0.f,0.f);
                        *(float4*)&xs[r * WROW + k16 + q * 4] = v;
                    }
                }
                __syncthreads();
                float a[4] = {0.f,0.f,0.f,0.f};
#pragma unroll 4
                for (int k = 0; k < 256; k += 4) {
                    float4 xv = *(const float4*)&xs[bl * WROW + k];
#pragma unroll
                    for (int g = 0; g < 4; g++) {
                        float4 wv = *(const float4*)&w0[(g * 16 + cl) * WROW + k];
                        a[g] = fmaf(xv.x,wv.x,fmaf(xv.y,wv.y,fmaf(xv.z,wv.z,fmaf(xv.w,wv.w,a[g]))));
                    }
                }
                float xg[4];
                if (t < VSTEP) {
                    const float* xr = g_xg1 + ((size_t)t * BATCH + b) * 1024;
#pragma unroll
                    for (int g = 0; g < 4; g++) xg[g] = xr[g * 256 + c];
                } else {
#pragma unroll
                    for (int g = 0; g < 4; g++) xg[g] = g_bs1[g * 256 + c];
                }
                float cn = sigm(a[1]+xg[1]) * c_reg + sigm(a[0]+xg[0]) * tanhf(a[2]+xg[2]);
                float hn = sigm(a[3]+xg[3]) * tanhf(cn);
                c_reg = cn;
                g_vid[(size_t)t * BH + b * HID + c] = hn;
            }
        } else {
            if (s >= 1 && s <= VSTEP) {
                int t = s - 1;
                float a[4] = {0.f,0.f,0.f,0.f};
#pragma unroll
                for (int seg = 0; seg < 2; seg++) {
                    {
                        int r = tid >> 4, k16 = (tid & 15) << 4;
                        const float* hp = (seg == 0)
                            ? g_vid + (size_t)t * BH + (bt * 16 + r) * HID
                            : g_h2 + (size_t)((t + 1) & 1) * BH + (bt * 16 + r) * HID;
#pragma unroll
                        for (int q = 0; q < 4; q++)
                            *(float4*)&xs[r * WROW + k16 + q * 4] =
                                *(const float4*)(hp + k16 + q * 4);
                    }
                    __syncthreads();
                    const float* W = seg ? w1 : w0;
#pragma unroll 4
                    for (int k = 0; k < 256; k += 4) {
                        float4 xv = *(const float4*)&xs[bl * WROW + k];
#pragma unroll
                        for (int g = 0; g < 4; g++) {
                            float4 wv = *(const float4*)&W[(g * 16 + cl) * WROW + k];
                            a[g] = fmaf(xv.x,wv.x,fmaf(xv.y,wv.y,fmaf(xv.z,wv.z,fmaf(xv.w,wv.w,a[g]))));
                        }
                    }
                    __syncthreads();
                }
                float cn = sigm(a[1]+g_bs2[256+c]) * c_reg + sigm(a[0]+g_bs2[c]) * tanhf(a[2]+g_bs2[512+c]);
                float hn = sigm(a[3]+g_bs2[768+c]) * tanhf(cn);
                c_reg = cn;
                g_h2[(size_t)(t & 1) * BH + b * HID + c] = hn;
                if (t == VSTEP - 1) g_c2[b * HID + c] = cn;
            }
        }
    }
}

// decode cell: gates = emb[tok]@wih[:, :256]^T + h@whh^T + xgd[t]
__global__ __launch_bounds__(256) void k_dec_cell(
    const float* __restrict__ emb, const float* __restrict__ wih,
    const float* __restrict__ whh, const float* __restrict__ xgd,
    const float* __restrict__ h_in, float* __restrict__ h_out, float* __restrict__ c_st,
    float* __restrict__ caption, int t)
{
    __shared__ float xs[16][68];
    __shared__ float ws[4][16][68];
    __shared__ int stok[16];
    int tid = threadIdx.x, bl = tid & 15, cl = tid >> 4;
    int ct = blockIdx.x, bt = blockIdx.y;
    int b = bt * 16 + bl, c = ct * 16 + cl;
    const unsigned long long* gprev = g_gmax[(t ^ 1) & 1];
    if (tid < 16) stok[tid] = (t == 0) ? 0 : dec_tok(gprev[bt * 16 + tid]);
    if (ct == 0 && bt == 0 && tid < BATCH) {
        if (t > 0 && caption) caption[tid * DEC + (t - 1)] = (float)dec_tok(gprev[tid]);
        g_gmax[t & 1][tid] = 0ull;
    }
    __syncthreads();
    float a0=0.f,a1=0.f,a2=0.f,a3=0.f;
    for (int seg = 0; seg < 2; seg++) {
        for (int k0 = 0; k0 < HID; k0 += 64) {
            { int r = tid >> 4, kq = (tid & 15) << 2;
              const float* src = (seg==0) ? emb + (size_t)stok[r]*HID
                                          : h_in + (bt*16+r)*HID;
              *(float4*)&xs[r][kq] = *(const float4*)(src + k0 + kq); }
#pragma unroll
            for (int i = 0; i < 4; i++) {
                int idx = tid + i*256, r = idx >> 4, kq = (idx & 15) << 2;
                int gg = r >> 4, cr = r & 15;
                const float* wr = (seg==0) ? wih + (size_t)(gg*HID + ct*16 + cr)*512
                                           : whh + (size_t)(gg*HID + ct*16 + cr)*HID;
                *(float4*)&ws[gg][cr][kq] = *(const float4*)(wr + k0 + kq);
            }
            __syncthreads();
#pragma unroll 8
            for (int k4 = 0; k4 < 64; k4 += 4) {
                float4 xv = *(const float4*)&xs[bl][k4];
                float4 w0 = *(const float4*)&ws[0][cl][k4];
                float4 w1 = *(const float4*)&ws[1][cl][k4];
                float4 w2v= *(const float4*)&ws[2][cl][k4];
                float4 w3 = *(const float4*)&ws[3][cl][k4];
                a0=fmaf(xv.x,w0.x,fmaf(xv.y,w0.y,fmaf(xv.z,w0.z,fmaf(xv.w,w0.w,a0))));
                a1=fmaf(xv.x,w1.x,fmaf(xv.y,w1.y,fmaf(xv.z,w1.z,fmaf(xv.w,w1.w,a1))));
                a2=fmaf(xv.x,w2v.x,fmaf(xv.y,w2v.y,fmaf(xv.z,w2v.z,fmaf(xv.w,w2v.w,a2))));
                a3=fmaf(xv.x,w3.x,fmaf(xv.y,w3.y,fmaf(xv.z,w3.z,fmaf(xv.w,w3.w,a3))));
            }
            __syncthreads();
        }
    }
    const float* xr = xgd + ((size_t)t * BATCH + b) * 1024;
    float cn = sigm(a1 + xr[256+c]) * c_st[b*HID+c] + sigm(a0 + xr[c]) * tanhf(a2 + xr[512+c]);
    float hn = sigm(a3 + xr[768+c]) * tanhf(cn);
    c_st[b*HID+c] = cn;
    h_out[b*HID+c] = hn;
}

// logits[64,32000] = h @ w2t + b2 ; direct coalesced LDG from transposed w2, no ws staging
__global__ __launch_bounds__(512) void k_logits(
    const float* __restrict__ h, const float* __restrict__ b2,
    float* __restrict__ prob, int t, int par)
{
    __shared__ float hs[64][64];
    int tid = threadIdx.x, tn = tid & 31, tw = tid >> 5;
    int b0 = tw * 4;
    int n0 = blockIdx.x * 256 + tn * 8;
    float acc[4][8];
#pragma unroll
    for (int i = 0; i < 4; i++)
#pragma unroll
        for (int j = 0; j < 8; j++) acc[i][j] = 0.f;

    const float* wp = g_w2t + n0;
    for (int kc = 0; kc < 4; kc++) {
#pragma unroll
        for (int i2 = 0; i2 < 2; i2++) {
            int idx = tid + i2 * 512, r = idx >> 4, kq = (idx & 15) << 2;
            *(float4*)&hs[r][kq] = *(const float4*)(h + r * HID + kc * 64 + kq);
        }
        __syncthreads();
        const float* wk = wp + (size_t)kc * 64 * VOCAB;
#pragma unroll 8
        for (int k = 0; k < 64; k++) {
            float4 w0 = *(const float4*)(wk);
            float4 w1 = *(const float4*)(wk + 4);
            wk += VOCAB;
#pragma unroll
            for (int i = 0; i < 4; i++) {
                float hv = hs[b0 + i][k];
                acc[i][0] = fmaf(hv, w0.x, acc[i][0]);
                acc[i][1] = fmaf(hv, w0.y, acc[i][1]);
                acc[i][2] = fmaf(hv, w0.z, acc[i][2]);
                acc[i][3] = fmaf(hv, w0.w, acc[i][3]);
                acc[i][4] = fmaf(hv, w1.x, acc[i][4]);
                acc[i][5] = fmaf(hv, w1.y, acc[i][5]);
                acc[i][6] = fmaf(hv, w1.z, acc[i][6]);
                acc[i][7] = fmaf(hv, w1.w, acc[i][7]);
            }
        }
        __syncthreads();
    }

    float4 bb0 = *(const float4*)(b2 + n0);
    float4 bb1 = *(const float4*)(b2 + n0 + 4);
    float bv[8] = {bb0.x, bb0.y, bb0.z, bb0.w, bb1.x, bb1.y, bb1.z, bb1.w};
    unsigned long long pk[4];
#pragma unroll
    for (int i = 0; i < 4; i++) {
        int b = b0 + i;
        float v[8];
#pragma unroll
        for (int j = 0; j < 8; j++) v[j] = acc[i][j] + bv[j];
        float* row = prob + ((size_t)b * DEC + t) * VOCAB + n0;
        *(float4*)row = make_float4(v[0], v[1], v[2], v[3]);
        *(float4*)(row + 4) = make_float4(v[4], v[5], v[6], v[7]);
        float vb = v[0]; int ni = 0;
#pragma unroll
        for (int j = 1; j < 8; j++) if (v[j] > vb) { vb = v[j]; ni = j; }
        pk[i] = ((unsigned long long)f2ord(vb) << 32) |
                (unsigned long long)(0xFFFFFFFFu - (unsigned)(n0 + ni));
    }
#pragma unroll
    for (int off = 16; off; off >>= 1)
#pragma unroll
        for (int i = 0; i < 4; i++)
            pk[i] = pkmax(pk[i], __shfl_xor_sync(0xFFFFFFFFu, pk[i], off));
    if (tn == 0)
#pragma unroll
        for (int i = 0; i < 4; i++) atomicMax(&g_gmax[par][b0 + i], pk[i]);
}

__global__ void k_final(float* cap) {
    int b = threadIdx.x;
    if (cap && b < BATCH) cap[b * DEC + DEC - 1] = (float)dec_tok(g_gmax[(DEC - 1) & 1][b]);
}

extern "C" void kernel_launch(void* const* d_in, const int* in_sizes, int n_in,
                              void* d_out, int out_size) {
    const float* video  = (const float*)d_in[0];
    const float* w1     = (const float*)d_in[1];
    const float* b1     = (const float*)d_in[2];
    const float* w2     = (const float*)d_in[3];
    const float* b2     = (const float*)d_in[4];
    const float* l1_wih = (const float*)d_in[5];
    const float* l1_whh = (const float*)d_in[6];
    const float* l1_bih = (const float*)d_in[7];
    const float* l1_bhh = (const float*)d_in[8];
    const float* l2_wih = (const float*)d_in[9];
    const float* l2_whh = (const float*)d_in[10];
    const float* l2_bih = (const float*)d_in[11];
    const float* l2_bhh = (const float*)d_in[12];
    const float* emb    = (const float*)d_in[13];

    float *pv,*pxg1,*pxgd,*pvid,*pc2,*ph2,*pbs1,*pbs2;
    cudaGetSymbolAddress((void**)&pv,   g_v);
    cudaGetSymbolAddress((void**)&pxg1, g_xg1);
    cudaGetSymbolAddress((void**)&pxgd, g_xg2);
    cudaGetSymbolAddress((void**)&pvid, g_vid);
    cudaGetSymbolAddress((void**)&pc2,  g_c2);
    cudaGetSymbolAddress((void**)&ph2,  g_h2);
    cudaGetSymbolAddress((void**)&pbs1, g_bs1);
    cudaGetSymbolAddress((void**)&pbs2, g_bs2);

    float* cap = nullptr;
    float* prob = (float*)d_out;
    long long need = (long long)BATCH*DEC + (long long)BATCH*DEC*VOCAB;
    if ((long long)out_size >= need) { cap = (float*)d_out; prob = (float*)d_out + BATCH*DEC; }

    static int attr_set = 0;
    const int ENC_SMEM = (2 * 4 * 16 * WROW + 16 * WROW) * 4;
    if (!attr_set) {
        cudaFuncSetAttribute(k_enc, cudaFuncAttributeMaxDynamicSharedMemorySize, ENC_SMEM);
        attr_set = 1;
    }

    k_zero<<<64, 256>>>();
    k_bias<<<4, 256>>>(l1_bih, l1_bhh, l2_bih, l2_bhh);
    k_tr<<<dim3(1000, 8), 256>>>(w2);

    // v[t,b,:] = video @ w1^T + b1  (t-major)
    k_gemm64<<<dim3(80, 4), 256>>>(video, FRAME, w1, FRAME, b1, pv, HID, FRAME, VSTEP);
    // xg1 = v @ l1_wih^T + bs1
    k_gemm<<<dim3(40, 16), 256>>>(pv, HID, l1_wih, HID, 0, pbs1, pxg1, 4*HID, HID, 0);

    // fused persistent LSTM1 + LSTM2 encoder
    k_enc<<<NBLK_ENC, 256, ENC_SMEM>>>(l1_whh, l2_wih, l2_whh);

    // xgd = vid_out[80:129] @ l2_wih[:,256:]^T + bs2
    k_gemm<<<dim3(25, 16), 256>>>(pvid + (size_t)VSTEP*BH, HID, l2_wih, 2*HID, HID,
                                  pbs2, pxgd, 4*HID, HID, 0);

    // autoregressive decode
    for (int t = 0; t < DEC; t++) {
        const float* hin = ph2 + ((t + 1) & 1) * BH;
        float* hout = ph2 + (t & 1) * BH;
        k_dec_cell<<<dim3(16, 4), 256>>>(emb, l2_wih, l2_whh, pxgd, hin, hout, pc2, cap, t);
        k_logits<<<125, 512>>>(hout, b2, prob, t, t & 1);
    }
    k_final<<<1, 64>>>(cap);
}

// round 15
// speedup vs baseline: 1.1077x; 1.1077x over previous
#include <cuda_runtime.h>
#include <math.h>

#define VOCAB 32000
#define BATCH 64
#define FRAME 4096
#define HID 256
#define VSTEP 80
#define CSTEP 50
#define TSTEPS (VSTEP + CSTEP - 1)
#define DEC (CSTEP - 1)
#define BH (BATCH * HID)
#define NBLK_ENC 128
#define ENC_ITERS 130

__device__ float g_v  [VSTEP * BATCH * HID];
__device__ float g_xg1[VSTEP * BATCH * 4 * HID];
__device__ float g_xg2[VSTEP * BATCH * 4 * HID];   // reused as xgd
__device__ float g_vid[(TSTEPS + 1) * BATCH * HID];
__device__ float g_c2 [BH];
__device__ float g_h2 [2 * BH];
__device__ float g_bs1[4 * HID];
__device__ float g_bs2[4 * HID];
__device__ unsigned long long g_gmax[2][BATCH];
__device__ int g_bar_sense;
__device__ unsigned g_bar_count;

__device__ __forceinline__ unsigned f2ord(float f) {
    unsigned u = __float_as_uint(f);
    return (u & 0x80000000u) ? ~u : (u | 0x80000000u);
}
__device__ __forceinline__ float sigm(float x) { return 1.f / (1.f + expf(-x)); }
__device__ __forceinline__ int dec_tok(unsigned long long p) {
    return (int)(0xFFFFFFFFu - (unsigned)(p & 0xFFFFFFFFull));
}
__device__ __forceinline__ unsigned long long pkmax(unsigned long long a, unsigned long long b) {
    return a > b ? a : b;
}

__global__ void k_zero() {
    int i = blockIdx.x * blockDim.x + threadIdx.x;
    if (i < BH) { g_h2[i] = 0.f; g_h2[BH + i] = 0.f; }
}
__global__ void k_bias(const float* a1, const float* b1, const float* a2, const float* b2) {
    int i = blockIdx.x * 256 + threadIdx.x;
    if (i < 4 * HID) { g_bs1[i] = a1[i] + b1[i]; g_bs2[i] = a2[i] + b2[i]; }
}

// 128x64 tile GEMM (K=256 hoists)
__global__ __launch_bounds__(256) void k_gemm(
    const float* __restrict__ A, int lda,
    const float* __restrict__ W, int ldw, int wcol,
    const float* __restrict__ bias,
    float* __restrict__ C, int ldc, int K, int permT)
{
    __shared__ float As[16][132];
    __shared__ float Bs[16][68];
    int tid = threadIdx.x, tx = tid & 15, ty = tid >> 4;
    int m0 = blockIdx.x * 128, n0 = blockIdx.y * 64;
    float4 acc[8];
#pragma unroll
    for (int i = 0; i < 8; i++) acc[i] = make_float4(0.f,0.f,0.f,0.f);
    for (int k0 = 0; k0 < K; k0 += 16) {
#pragma unroll
        for (int i = 0; i < 2; i++) {
            int idx = tid + i * 256, r = idx >> 2, kq = (idx & 3) << 2;
            float4 va = *(const float4*)(A + (size_t)(m0 + r) * lda + k0 + kq);
            As[kq][r]=va.x; As[kq+1][r]=va.y; As[kq+2][r]=va.z; As[kq+3][r]=va.w;
        }
        {
            int r = tid >> 2, kq = (tid & 3) << 2;
            float4 vb = *(const float4*)(W + (size_t)(n0 + r) * ldw + wcol + k0 + kq);
            Bs[kq][r]=vb.x; Bs[kq+1][r]=vb.y; Bs[kq+2][r]=vb.z; Bs[kq+3][r]=vb.w;
        }
        __syncthreads();
#pragma unroll
        for (int k = 0; k < 16; k++) {
            float4 b4 = *(const float4*)&Bs[k][tx * 4];
            float4 a0 = *(const float4*)&As[k][ty * 8];
            float4 a1 = *(const float4*)&As[k][ty * 8 + 4];
            float av[8] = {a0.x,a0.y,a0.z,a0.w,a1.x,a1.y,a1.z,a1.w};
#pragma unroll
            for (int i = 0; i < 8; i++) {
                acc[i].x = fmaf(av[i], b4.x, acc[i].x);
                acc[i].y = fmaf(av[i], b4.y, acc[i].y);
                acc[i].z = fmaf(av[i], b4.z, acc[i].z);
                acc[i].w = fmaf(av[i], b4.w, acc[i].w);
            }
        }
        __syncthreads();
    }
    float4 bb = *(const float4*)(bias + n0 + tx * 4);
#pragma unroll
    for (int i = 0; i < 8; i++) {
        int m = m0 + ty * 8 + i;
        int orow = permT ? ((m % permT) * BATCH + m / permT) : m;
        *(float4*)(C + (size_t)orow * ldc + n0 + tx * 4) =
            make_float4(acc[i].x+bb.x, acc[i].y+bb.y, acc[i].z+bb.z, acc[i].w+bb.w);
    }
}

// 64x64 tile GEMM, software-pipelined (reg prefetch + double-buffered smem)
__global__ __launch_bounds__(256) void k_gemm64(
    const float* __restrict__ A, int lda,
    const float* __restrict__ W, int ldw,
    const float* __restrict__ bias,
    float* __restrict__ C, int ldc, int K, int permT)
{
    __shared__ float As[2][16][68];
    __shared__ float Bs[2][16][68];
    int tid = threadIdx.x, tx = tid & 15, ty = tid >> 4;
    int m0 = blockIdx.x * 64, n0 = blockIdx.y * 64;
    int r = tid >> 2, kq = (tid & 3) << 2;
    const float* Ap = A + (size_t)(m0 + r) * lda + kq;
    const float* Wp = W + (size_t)(n0 + r) * ldw + kq;
    int nchunk = K >> 4;

    float4 ra = *(const float4*)Ap;
    float4 rb = *(const float4*)Wp;
    As[0][kq][r]=ra.x; As[0][kq+1][r]=ra.y; As[0][kq+2][r]=ra.z; As[0][kq+3][r]=ra.w;
    Bs[0][kq][r]=rb.x; Bs[0][kq+1][r]=rb.y; Bs[0][kq+2][r]=rb.z; Bs[0][kq+3][r]=rb.w;
    __syncthreads();

    float4 acc[4];
#pragma unroll
    for (int i = 0; i < 4; i++) acc[i] = make_float4(0.f,0.f,0.f,0.f);

    for (int kc = 0; kc < nchunk; kc++) {
        int buf = kc & 1;
        if (kc + 1 < nchunk) {
            ra = *(const float4*)(Ap + (kc + 1) * 16);
            rb = *(const float4*)(Wp + (kc + 1) * 16);
        }
#pragma unroll
        for (int k = 0; k < 16; k++) {
            float4 b4 = *(const float4*)&Bs[buf][k][tx * 4];
            float4 a4 = *(const float4*)&As[buf][k][ty * 4];
            float av[4] = {a4.x, a4.y, a4.z, a4.w};
#pragma unroll
            for (int i = 0; i < 4; i++) {
                acc[i].x = fmaf(av[i], b4.x, acc[i].x);
                acc[i].y = fmaf(av[i], b4.y, acc[i].y);
                acc[i].z = fmaf(av[i], b4.z, acc[i].z);
                acc[i].w = fmaf(av[i], b4.w, acc[i].w);
            }
        }
        if (kc + 1 < nchunk) {
            int nb = buf ^ 1;
            As[nb][kq][r]=ra.x; As[nb][kq+1][r]=ra.y; As[nb][kq+2][r]=ra.z; As[nb][kq+3][r]=ra.w;
            Bs[nb][kq][r]=rb.x; Bs[nb][kq+1][r]=rb.y; Bs[nb][kq+2][r]=rb.z; Bs[nb][kq+3][r]=rb.w;
            __syncthreads();
        }
    }
    float4 bb = *(const float4*)(bias + n0 + tx * 4);
#pragma unroll
    for (int i = 0; i < 4; i++) {
        int m = m0 + ty * 4 + i;
        int orow = permT ? ((m % permT) * BATCH + m / permT) : m;
        *(float4*)(C + (size_t)orow * ldc + n0 + tx * 4) =
            make_float4(acc[i].x+bb.x, acc[i].y+bb.y, acc[i].z+bb.z, acc[i].w+bb.w);
    }
}

// ---- persistent fused encoder: blocks 0..63 = LSTM1, 64..127 = LSTM2-enc ----
#define WROW 260
__global__ __launch_bounds__(256) void k_enc(
    const float* __restrict__ l1_whh, const float* __restrict__ l2_wih,
    const float* __restrict__ l2_whh)
{
    extern __shared__ float sm[];
    float* w0 = sm;
    float* w1 = sm + 4 * 16 * WROW;
    float* xs = sm + 2 * 4 * 16 * WROW;

    int tid = threadIdx.x, bl = tid & 15, cl = tid >> 4;
    int bid = blockIdx.x;
    int role = bid >> 6;
    int lb = bid & 63, ct = lb & 15, bt = lb >> 4;
    int b = bt * 16 + bl, c = ct * 16 + cl;

    for (int i = tid; i < 4096; i += 256) {
        int row = i >> 6, kq = (i & 63) << 2;
        int g = row >> 4, cr = row & 15;
        int wrow = g * 256 + ct * 16 + cr;
        float* dst = w0 + (g * 16 + cr) * WROW + kq;
        if (role == 0) {
            float4 v = *(const float4*)(l1_whh + (size_t)wrow * 256 + kq);
            dst[0]=v.x; dst[1]=v.y; dst[2]=v.z; dst[3]=v.w;
        } else {
            float4 v = *(const float4*)(l2_wih + (size_t)wrow * 512 + 256 + kq);
            dst[0]=v.x; dst[1]=v.y; dst[2]=v.z; dst[3]=v.w;
            float4 u = *(const float4*)(l2_whh + (size_t)wrow * 256 + kq);
            float* d2 = w1 + (g * 16 + cr) * WROW + kq;
            d2[0]=u.x; d2[1]=u.y; d2[2]=u.z; d2[3]=u.w;
        }
    }

    float c_reg = 0.f;
    int sense = 0;
    volatile int* vsense = &g_bar_sense;

    for (int s = 0; s < ENC_ITERS; s++) {
        __syncthreads();
        if (tid == 0) {
            __threadfence();
            sense ^= 1;
            unsigned old = atomicAdd(&g_bar_count, 1u);
            if (old == (unsigned)(NBLK_ENC - 1)) {
                g_bar_count = 0u;
                __threadfence();
                *vsense = sense;
            } else {
                while (*vsense != sense) __nanosleep(64);
                __threadfence();
            }
        }
        __syncthreads();

        if (role == 0) {
            if (s < TSTEPS) {
                int t = s;
                {
                    int r = tid >> 4, k16 = (tid & 15) << 4;
                    const float* hp = (t == 0) ? (const float*)0
                        : g_vid + (size_t)(t - 1) * BH + (bt * 16 + r) * HID;
#pragma unroll
                    for (int q = 0; q < 4; q++) {
                        float4 v = hp ? *(const float4*)(hp + k16 + q * 4)
                                      : make_float4(0.f,0.f,0.f,0.f);
                        *(float4*)&xs[r * WROW + k16 + q * 4] = v;
                    }
                }
                __syncthreads();
                float a[4] = {0.f,0.f,0.f,0.f};
#pragma unroll 4
                for (int k = 0; k < 256; k += 4) {
                    float4 xv = *(const float4*)&xs[bl * WROW + k];
#pragma unroll
                    for (int g = 0; g < 4; g++) {
                        float4 wv = *(const float4*)&w0[(g * 16 + cl) * WROW + k];
                        a[g] = fmaf(xv.x,wv.x,fmaf(xv.y,wv.y,fmaf(xv.z,wv.z,fmaf(xv.w,wv.w,a[g]))));
                    }
                }
                float xg[4];
                if (t < VSTEP) {
                    const float* xr = g_xg1 + ((size_t)t * BATCH + b) * 1024;
#pragma unroll
                    for (int g = 0; g < 4; g++) xg[g] = xr[g * 256 + c];
                } else {
#pragma unroll
                    for (int g = 0; g < 4; g++) xg[g] = g_bs1[g * 256 + c];
                }
                float cn = sigm(a[1]+xg[1]) * c_reg + sigm(a[0]+xg[0]) * tanhf(a[2]+xg[2]);
                float hn = sigm(a[3]+xg[3]) * tanhf(cn);
                c_reg = cn;
                g_vid[(size_t)t * BH + b * HID + c] = hn;
            }
        } else {
            if (s >= 1 && s <= VSTEP) {
                int t = s - 1;
                float a[4] = {0.f,0.f,0.f,0.f};
#pragma unroll
                for (int seg = 0; seg < 2; seg++) {
                    {
                        int r = tid >> 4, k16 = (tid & 15) << 4;
                        const float* hp = (seg == 0)
                            ? g_vid + (size_t)t * BH + (bt * 16 + r) * HID
                            : g_h2 + (size_t)((t + 1) & 1) * BH + (bt * 16 + r) * HID;
#pragma unroll
                        for (int q = 0; q < 4; q++)
                            *(float4*)&xs[r * WROW + k16 + q * 4] =
                                *(const float4*)(hp + k16 + q * 4);
                    }
                    __syncthreads();
                    const float* W = seg ? w1 : w0;
#pragma unroll 4
                    for (int k = 0; k < 256; k += 4) {
                        float4 xv = *(const float4*)&xs[bl * WROW + k];
#pragma unroll
                        for (int g = 0; g < 4; g++) {
                            float4 wv = *(const float4*)&W[(g * 16 + cl) * WROW + k];
                            a[g] = fmaf(xv.x,wv.x,fmaf(xv.y,wv.y,fmaf(xv.z,wv.z,fmaf(xv.w,wv.w,a[g]))));
                        }
                    }
                    __syncthreads();
                }
                float cn = sigm(a[1]+g_bs2[256+c]) * c_reg + sigm(a[0]+g_bs2[c]) * tanhf(a[2]+g_bs2[512+c]);
                float hn = sigm(a[3]+g_bs2[768+c]) * tanhf(cn);
                c_reg = cn;
                g_h2[(size_t)(t & 1) * BH + b * HID + c] = hn;
                if (t == VSTEP - 1) g_c2[b * HID + c] = cn;
            }
        }
    }
}

// decode cell: gates = emb[tok]@wih[:, :256]^T + h@whh^T + xgd[t]
__global__ __launch_bounds__(256) void k_dec_cell(
    const float* __restrict__ emb, const float* __restrict__ wih,
    const float* __restrict__ whh, const float* __restrict__ xgd,
    const float* __restrict__ h_in, float* __restrict__ h_out, float* __restrict__ c_st,
    float* __restrict__ caption, int t)
{
    __shared__ float xs[16][68];
    __shared__ float ws[4][16][68];
    __shared__ int stok[16];
    int tid = threadIdx.x, bl = tid & 15, cl = tid >> 4;
    int ct = blockIdx.x, bt = blockIdx.y;
    int b = bt * 16 + bl, c = ct * 16 + cl;
    const unsigned long long* gprev = g_gmax[(t ^ 1) & 1];
    if (tid < 16) stok[tid] = (t == 0) ? 0 : dec_tok(gprev[bt * 16 + tid]);
    if (ct == 0 && bt == 0 && tid < BATCH) {
        if (t > 0 && caption) caption[tid * DEC + (t - 1)] = (float)dec_tok(gprev[tid]);
        g_gmax[t & 1][tid] = 0ull;
    }
    __syncthreads();
    float a0=0.f,a1=0.f,a2=0.f,a3=0.f;
    for (int seg = 0; seg < 2; seg++) {
        for (int k0 = 0; k0 < HID; k0 += 64) {
            { int r = tid >> 4, kq = (tid & 15) << 2;
              const float* src = (seg==0) ? emb + (size_t)stok[r]*HID
                                          : h_in + (bt*16+r)*HID;
              *(float4*)&xs[r][kq] = *(const float4*)(src + k0 + kq); }
#pragma unroll
            for (int i = 0; i < 4; i++) {
                int idx = tid + i*256, r = idx >> 4, kq = (idx & 15) << 2;
                int gg = r >> 4, cr = r & 15;
                const float* wr = (seg==0) ? wih + (size_t)(gg*HID + ct*16 + cr)*512
                                           : whh + (size_t)(gg*HID + ct*16 + cr)*HID;
                *(float4*)&ws[gg][cr][kq] = *(const float4*)(wr + k0 + kq);
            }
            __syncthreads();
#pragma unroll 8
            for (int k4 = 0; k4 < 64; k4 += 4) {
                float4 xv = *(const float4*)&xs[bl][k4];
                float4 w0 = *(const float4*)&ws[0][cl][k4];
                float4 w1 = *(const float4*)&ws[1][cl][k4];
                float4 w2v= *(const float4*)&ws[2][cl][k4];
                float4 w3 = *(const float4*)&ws[3][cl][k4];
                a0=fmaf(xv.x,w0.x,fmaf(xv.y,w0.y,fmaf(xv.z,w0.z,fmaf(xv.w,w0.w,a0))));
                a1=fmaf(xv.x,w1.x,fmaf(xv.y,w1.y,fmaf(xv.z,w1.z,fmaf(xv.w,w1.w,a1))));
                a2=fmaf(xv.x,w2v.x,fmaf(xv.y,w2v.y,fmaf(xv.z,w2v.z,fmaf(xv.w,w2v.w,a2))));
                a3=fmaf(xv.x,w3.x,fmaf(xv.y,w3.y,fmaf(xv.z,w3.z,fmaf(xv.w,w3.w,a3))));
            }
            __syncthreads();
        }
    }
    const float* xr = xgd + ((size_t)t * BATCH + b) * 1024;
    float cn = sigm(a1 + xr[256+c]) * c_st[b*HID+c] + sigm(a0 + xr[c]) * tanhf(a2 + xr[512+c]);
    float hn = sigm(a3 + xr[768+c]) * tanhf(cn);
    c_st[b*HID+c] = cn;
    h_out[b*HID+c] = hn;
}

// logits[64,32000] = h @ w2^T + b2 ; exact fp32, conflict-free, 512 threads / 16 warps
__global__ __launch_bounds__(512) void k_logits(
    const float* __restrict__ h, const float* __restrict__ w2, const float* __restrict__ b2,
    float* __restrict__ prob, int t, int par)
{
    __shared__ float hs[64][36];
    __shared__ float ws[32 * 257];
    int tid = threadIdx.x, tn = tid & 31, tw = tid >> 5;
    int b0 = tw * 4, nb = blockIdx.x * 256;
    float acc[4][8];
#pragma unroll
    for (int i = 0; i < 4; i++)
#pragma unroll
        for (int j = 0; j < 8; j++) acc[i][j] = 0.f;

    for (int k0 = 0; k0 < HID; k0 += 32) {
        {
            int r = tid >> 3, kq = (tid & 7) << 2;
            *(float4*)&hs[r][kq] = *(const float4*)(h + r * HID + k0 + kq);
        }
#pragma unroll
        for (int i = 0; i < 4; i++) {
            int idx = tid + i * 512, r = idx >> 3, kq = (idx & 7) << 2;
            float4 v = *(const float4*)(w2 + (size_t)(nb + r) * HID + k0 + kq);
            ws[(kq + 0) * 257 + r] = v.x; ws[(kq + 1) * 257 + r] = v.y;
            ws[(kq + 2) * 257 + r] = v.z; ws[(kq + 3) * 257 + r] = v.w;
        }
        __syncthreads();
#pragma unroll 4
        for (int k = 0; k < 32; k++) {
            float wv[8];
#pragma unroll
            for (int j = 0; j < 8; j++) wv[j] = ws[k * 257 + tn + 32 * j];
#pragma unroll
            for (int i = 0; i < 4; i++) {
                float hv = hs[b0 + i][k];
#pragma unroll
                for (int j = 0; j < 8; j++) acc[i][j] = fmaf(hv, wv[j], acc[i][j]);
            }
        }
        __syncthreads();
    }
    float b2v[8];
#pragma unroll
    for (int j = 0; j < 8; j++) b2v[j] = b2[nb + tn + 32 * j];
    unsigned long long pk[4];
#pragma unroll
    for (int i = 0; i < 4; i++) {
        int b = b0 + i;
        float* row = prob + ((size_t)b * DEC + t) * VOCAB + nb;
        float vb = -1e30f; int ni = 0;
#pragma unroll
        for (int j = 0; j < 8; j++) {
            int n = tn + 32 * j;
            float v = acc[i][j] + b2v[j];
            row[n] = v;
            if (v > vb) { vb = v; ni = n; }
        }
        pk[i] = ((unsigned long long)f2ord(vb) << 32) |
                (unsigned long long)(0xFFFFFFFFu - (unsigned)(nb + ni));
    }
#pragma unroll
    for (int off = 16; off; off >>= 1)
#pragma unroll
        for (int i = 0; i < 4; i++)
            pk[i] = pkmax(pk[i], __shfl_xor_sync(0xFFFFFFFFu, pk[i], off));
    if (tn == 0)
#pragma unroll
        for (int i = 0; i < 4; i++) atomicMax(&g_gmax[par][b0 + i], pk[i]);
}

__global__ void k_final(float* cap) {
    int b = threadIdx.x;
    if (cap && b < BATCH) cap[b * DEC + DEC - 1] = (float)dec_tok(g_gmax[(DEC - 1) & 1][b]);
}

extern "C" void kernel_launch(void* const* d_in, const int* in_sizes, int n_in,
                              void* d_out, int out_size) {
    const float* video  = (const float*)d_in[0];
    const float* w1     = (const float*)d_in[1];
    const float* b1     = (const float*)d_in[2];
    const float* w2     = (const float*)d_in[3];
    const float* b2     = (const float*)d_in[4];
    const float* l1_wih = (const float*)d_in[5];
    const float* l1_whh = (const float*)d_in[6];
    const float* l1_bih = (const float*)d_in[7];
    const float* l1_bhh = (const float*)d_in[8];
    const float* l2_wih = (const float*)d_in[9];
    const float* l2_whh = (const float*)d_in[10];
    const float* l2_bih = (const float*)d_in[11];
    const float* l2_bhh = (const float*)d_in[12];
    const float* emb    = (const float*)d_in[13];

    float *pv,*pxg1,*pxgd,*pvid,*pc2,*ph2,*pbs1,*pbs2;
    cudaGetSymbolAddress((void**)&pv,   g_v);
    cudaGetSymbolAddress((void**)&pxg1, g_xg1);
    cudaGetSymbolAddress((void**)&pxgd, g_xg2);
    cudaGetSymbolAddress((void**)&pvid, g_vid);
    cudaGetSymbolAddress((void**)&pc2,  g_c2);
    cudaGetSymbolAddress((void**)&ph2,  g_h2);
    cudaGetSymbolAddress((void**)&pbs1, g_bs1);
    cudaGetSymbolAddress((void**)&pbs2, g_bs2);

    float* cap = nullptr;
    float* prob = (float*)d_out;
    long long need = (long long)BATCH*DEC + (long long)BATCH*DEC*VOCAB;
    if ((long long)out_size >= need) { cap = (float*)d_out; prob = (float*)d_out + BATCH*DEC; }

    static int attr_set = 0;
    const int ENC_SMEM = (2 * 4 * 16 * WROW + 16 * WROW) * 4;
    if (!attr_set) {
        cudaFuncSetAttribute(k_enc, cudaFuncAttributeMaxDynamicSharedMemorySize, ENC_SMEM);
        attr_set = 1;
    }

    k_zero<<<64, 256>>>();
    k_bias<<<4, 256>>>(l1_bih, l1_bhh, l2_bih, l2_bhh);

    // v[t,b,:] = video @ w1^T + b1  (t-major), pipelined 64x64 tiles
    k_gemm64<<<dim3(80, 4), 256>>>(video, FRAME, w1, FRAME, b1, pv, HID, FRAME, VSTEP);
    // xg1 = v @ l1_wih^T + bs1
    k_gemm<<<dim3(40, 16), 256>>>(pv, HID, l1_wih, HID, 0, pbs1, pxg1, 4*HID, HID, 0);

    // fused persistent LSTM1 + LSTM2 encoder
    k_enc<<<NBLK_ENC, 256, ENC_SMEM>>>(l1_whh, l2_wih, l2_whh);

    // xgd = vid_out[80:129] @ l2_wih[:,256:]^T + bs2
    k_gemm<<<dim3(25, 16), 256>>>(pvid + (size_t)VSTEP*BH, HID, l2_wih, 2*HID, HID,
                                  pbs2, pxgd, 4*HID, HID, 0);

    // autoregressive decode
    for (int t = 0; t < DEC; t++) {
        const float* hin = ph2 + ((t + 1) & 1) * BH;
        float* hout = ph2 + (t & 1) * BH;
        k_dec_cell<<<dim3(16, 4), 256>>>(emb, l2_wih, l2_whh, pxgd, hin, hout, pc2, cap, t);
        k_logits<<<125, 512>>>(hout, w2, b2, prob, t, t & 1);
    }
    k_final<<<1, 64>>>(cap);
}

// round 16
// speedup vs baseline: 1.1352x; 1.0248x over previous
#include <cuda_runtime.h>
#include <math.h>

#define VOCAB 32000
#define BATCH 64
#define FRAME 4096
#define HID 256
#define VSTEP 80
#define CSTEP 50
#define TSTEPS (VSTEP + CSTEP - 1)
#define DEC (CSTEP - 1)
#define BH (BATCH * HID)
#define NBLK_ENC 128
#define ENC_ITERS 130
#define NPB 224                 /* logits n-cols per block */
#define NBLK_LOG 143            /* 143*224 = 32032 >= 32000 */
#define WPAD 225

__device__ float g_v  [VSTEP * BATCH * HID];
__device__ float g_xg1[VSTEP * BATCH * 4 * HID];
__device__ float g_xg2[VSTEP * BATCH * 4 * HID];   // reused as xgd
__device__ float g_vid[(TSTEPS + 1) * BATCH * HID];
__device__ float g_c2 [BH];
__device__ float g_h2 [2 * BH];
__device__ float g_bs1[4 * HID];
__device__ float g_bs2[4 * HID];
__device__ unsigned long long g_gmax[2][BATCH];
__device__ int g_bar_sense;
__device__ unsigned g_bar_count;

__device__ __forceinline__ unsigned f2ord(float f) {
    unsigned u = __float_as_uint(f);
    return (u & 0x80000000u) ? ~u : (u | 0x80000000u);
}
__device__ __forceinline__ float sigm(float x) { return 1.f / (1.f + expf(-x)); }
__device__ __forceinline__ int dec_tok(unsigned long long p) {
    return (int)(0xFFFFFFFFu - (unsigned)(p & 0xFFFFFFFFull));
}
__device__ __forceinline__ unsigned long long pkmax(unsigned long long a, unsigned long long b) {
    return a > b ? a : b;
}

__global__ void k_zero() {
    int i = blockIdx.x * blockDim.x + threadIdx.x;
    if (i < BH) { g_h2[i] = 0.f; g_h2[BH + i] = 0.f; }
}
__global__ void k_bias(const float* a1, const float* b1, const float* a2, const float* b2) {
    int i = blockIdx.x * 256 + threadIdx.x;
    if (i < 4 * HID) { g_bs1[i] = a1[i] + b1[i]; g_bs2[i] = a2[i] + b2[i]; }
}

// 128x64 tile GEMM (K=256 hoists)
__global__ __launch_bounds__(256) void k_gemm(
    const float* __restrict__ A, int lda,
    const float* __restrict__ W, int ldw, int wcol,
    const float* __restrict__ bias,
    float* __restrict__ C, int ldc, int K, int permT)
{
    __shared__ float As[16][132];
    __shared__ float Bs[16][68];
    int tid = threadIdx.x, tx = tid & 15, ty = tid >> 4;
    int m0 = blockIdx.x * 128, n0 = blockIdx.y * 64;
    float4 acc[8];
#pragma unroll
    for (int i = 0; i < 8; i++) acc[i] = make_float4(0.f,0.f,0.f,0.f);
    for (int k0 = 0; k0 < K; k0 += 16) {
#pragma unroll
        for (int i = 0; i < 2; i++) {
            int idx = tid + i * 256, r = idx >> 2, kq = (idx & 3) << 2;
            float4 va = *(const float4*)(A + (size_t)(m0 + r) * lda + k0 + kq);
            As[kq][r]=va.x; As[kq+1][r]=va.y; As[kq+2][r]=va.z; As[kq+3][r]=va.w;
        }
        {
            int r = tid >> 2, kq = (tid & 3) << 2;
            float4 vb = *(const float4*)(W + (size_t)(n0 + r) * ldw + wcol + k0 + kq);
            Bs[kq][r]=vb.x; Bs[kq+1][r]=vb.y; Bs[kq+2][r]=vb.z; Bs[kq+3][r]=vb.w;
        }
        __syncthreads();
#pragma unroll
        for (int k = 0; k < 16; k++) {
            float4 b4 = *(const float4*)&Bs[k][tx * 4];
            float4 a0 = *(const float4*)&As[k][ty * 8];
            float4 a1 = *(const float4*)&As[k][ty * 8 + 4];
            float av[8] = {a0.x,a0.y,a0.z,a0.w,a1.x,a1.y,a1.z,a1.w};
#pragma unroll
            for (int i = 0; i < 8; i++) {
                acc[i].x = fmaf(av[i], b4.x, acc[i].x);
                acc[i].y = fmaf(av[i], b4.y, acc[i].y);
                acc[i].z = fmaf(av[i], b4.z, acc[i].z);
                acc[i].w = fmaf(av[i], b4.w, acc[i].w);
            }
        }
        __syncthreads();
    }
    float4 bb = *(const float4*)(bias + n0 + tx * 4);
#pragma unroll
    for (int i = 0; i < 8; i++) {
        int m = m0 + ty * 8 + i;
        int orow = permT ? ((m % permT) * BATCH + m / permT) : m;
        *(float4*)(C + (size_t)orow * ldc + n0 + tx * 4) =
            make_float4(acc[i].x+bb.x, acc[i].y+bb.y, acc[i].z+bb.z, acc[i].w+bb.w);
    }
}

// 64x64 tile GEMM, software-pipelined (reg prefetch + double-buffered smem)
__global__ __launch_bounds__(256) void k_gemm64(
    const float* __restrict__ A, int lda,
    const float* __restrict__ W, int ldw,
    const float* __restrict__ bias,
    float* __restrict__ C, int ldc, int K, int permT)
{
    __shared__ float As[2][16][68];
    __shared__ float Bs[2][16][68];
    int tid = threadIdx.x, tx = tid & 15, ty = tid >> 4;
    int m0 = blockIdx.x * 64, n0 = blockIdx.y * 64;
    int r = tid >> 2, kq = (tid & 3) << 2;
    const float* Ap = A + (size_t)(m0 + r) * lda + kq;
    const float* Wp = W + (size_t)(n0 + r) * ldw + kq;
    int nchunk = K >> 4;

    float4 ra = *(const float4*)Ap;
    float4 rb = *(const float4*)Wp;
    As[0][kq][r]=ra.x; As[0][kq+1][r]=ra.y; As[0][kq+2][r]=ra.z; As[0][kq+3][r]=ra.w;
    Bs[0][kq][r]=rb.x; Bs[0][kq+1][r]=rb.y; Bs[0][kq+2][r]=rb.z; Bs[0][kq+3][r]=rb.w;
    __syncthreads();

    float4 acc[4];
#pragma unroll
    for (int i = 0; i < 4; i++) acc[i] = make_float4(0.f,0.f,0.f,0.f);

    for (int kc = 0; kc < nchunk; kc++) {
        int buf = kc & 1;
        if (kc + 1 < nchunk) {
            ra = *(const float4*)(Ap + (kc + 1) * 16);
            rb = *(const float4*)(Wp + (kc + 1) * 16);
        }
#pragma unroll
        for (int k = 0; k < 16; k++) {
            float4 b4 = *(const float4*)&Bs[buf][k][tx * 4];
            float4 a4 = *(const float4*)&As[buf][k][ty * 4];
            float av[4] = {a4.x, a4.y, a4.z, a4.w};
#pragma unroll
            for (int i = 0; i < 4; i++) {
                acc[i].x = fmaf(av[i], b4.x, acc[i].x);
                acc[i].y = fmaf(av[i], b4.y, acc[i].y);
                acc[i].z = fmaf(av[i], b4.z, acc[i].z);
                acc[i].w = fmaf(av[i], b4.w, acc[i].w);
            }
        }
        if (kc + 1 < nchunk) {
            int nb = buf ^ 1;
            As[nb][kq][r]=ra.x; As[nb][kq+1][r]=ra.y; As[nb][kq+2][r]=ra.z; As[nb][kq+3][r]=ra.w;
            Bs[nb][kq][r]=rb.x; Bs[nb][kq+1][r]=rb.y; Bs[nb][kq+2][r]=rb.z; Bs[nb][kq+3][r]=rb.w;
            __syncthreads();
        }
    }
    float4 bb = *(const float4*)(bias + n0 + tx * 4);
#pragma unroll
    for (int i = 0; i < 4; i++) {
        int m = m0 + ty * 4 + i;
        int orow = permT ? ((m % permT) * BATCH + m / permT) : m;
        *(float4*)(C + (size_t)orow * ldc + n0 + tx * 4) =
            make_float4(acc[i].x+bb.x, acc[i].y+bb.y, acc[i].z+bb.z, acc[i].w+bb.w);
    }
}

// ---- persistent fused encoder: blocks 0..63 = LSTM1, 64..127 = LSTM2-enc ----
#define WROW 260
__global__ __launch_bounds__(256) void k_enc(
    const float* __restrict__ l1_whh, const float* __restrict__ l2_wih,
    const float* __restrict__ l2_whh)
{
    extern __shared__ float sm[];
    float* w0 = sm;
    float* w1 = sm + 4 * 16 * WROW;
    float* xs = sm + 2 * 4 * 16 * WROW;

    int tid = threadIdx.x, bl = tid & 15, cl = tid >> 4;
    int bid = blockIdx.x;
    int role = bid >> 6;
    int lb = bid & 63, ct = lb & 15, bt = lb >> 4;
    int b = bt * 16 + bl, c = ct * 16 + cl;

    for (int i = tid; i < 4096; i += 256) {
        int row = i >> 6, kq = (i & 63) << 2;
        int g = row >> 4, cr = row & 15;
        int wrow = g * 256 + ct * 16 + cr;
        float* dst = w0 + (g * 16 + cr) * WROW + kq;
        if (role == 0) {
            float4 v = *(const float4*)(l1_whh + (size_t)wrow * 256 + kq);
            dst[0]=v.x; dst[1]=v.y; dst[2]=v.z; dst[3]=v.w;
        } else {
            float4 v = *(const float4*)(l2_wih + (size_t)wrow * 512 + 256 + kq);
            dst[0]=v.x; dst[1]=v.y; dst[2]=v.z; dst[3]=v.w;
            float4 u = *(const float4*)(l2_whh + (size_t)wrow * 256 + kq);
            float* d2 = w1 + (g * 16 + cr) * WROW + kq;
            d2[0]=u.x; d2[1]=u.y; d2[2]=u.z; d2[3]=u.w;
        }
    }

    float c_reg = 0.f;
    int sense = 0;
    volatile int* vsense = &g_bar_sense;

    for (int s = 0; s < ENC_ITERS; s++) {
        __syncthreads();
        if (tid == 0) {
            __threadfence();
            sense ^= 1;
            unsigned old = atomicAdd(&g_bar_count, 1u);
            if (old == (unsigned)(NBLK_ENC - 1)) {
                g_bar_count = 0u;
                __threadfence();
                *vsense = sense;
            } else {
                while (*vsense != sense) __nanosleep(64);
                __threadfence();
            }
        }
        __syncthreads();

        if (role == 0) {
            if (s < TSTEPS) {
                int t = s;
                {
                    int r = tid >> 4, k16 = (tid & 15) << 4;
                    const float* hp = (t == 0) ? (const float*)0
                        : g_vid + (size_t)(t - 1) * BH + (bt * 16 + r) * HID;
#pragma unroll
                    for (int q = 0; q < 4; q++) {
                        float4 v = hp ? *(const float4*)(hp + k16 + q * 4)
                                      : make_float4(0.f,0.f,0.f,0.f);
                        *(float4*)&xs[r * WROW + k16 + q * 4] = v;
                    }
                }
                __syncthreads();
                float a[4] = {0.f,0.f,0.f,0.f};
#pragma unroll 4
                for (int k = 0; k < 256; k += 4) {
                    float4 xv = *(const float4*)&xs[bl * WROW + k];
#pragma unroll
                    for (int g = 0; g < 4; g++) {
                        float4 wv = *(const float4*)&w0[(g * 16 + cl) * WROW + k];
                        a[g] = fmaf(xv.x,wv.x,fmaf(xv.y,wv.y,fmaf(xv.z,wv.z,fmaf(xv.w,wv.w,a[g]))));
                    }
                }
                float xg[4];
                if (t < VSTEP) {
                    const float* xr = g_xg1 + ((size_t)t * BATCH + b) * 1024;
#pragma unroll
                    for (int g = 0; g < 4; g++) xg[g] = xr[g * 256 + c];
                } else {
#pragma unroll
                    for (int g = 0; g < 4; g++) xg[g] = g_bs1[g * 256 + c];
                }
                float cn = sigm(a[1]+xg[1]) * c_reg + sigm(a[0]+xg[0]) * tanhf(a[2]+xg[2]);
                float hn = sigm(a[3]+xg[3]) * tanhf(cn);
                c_reg = cn;
                g_vid[(size_t)t * BH + b * HID + c] = hn;
            }
        } else {
            if (s >= 1 && s <= VSTEP) {
                int t = s - 1;
                float a[4] = {0.f,0.f,0.f,0.f};
#pragma unroll
                for (int seg = 0; seg < 2; seg++) {
                    {
                        int r = tid >> 4, k16 = (tid & 15) << 4;
                        const float* hp = (seg == 0)
                            ? g_vid + (size_t)t * BH + (bt * 16 + r) * HID
                            : g_h2 + (size_t)((t + 1) & 1) * BH + (bt * 16 + r) * HID;
#pragma unroll
                        for (int q = 0; q < 4; q++)
                            *(float4*)&xs[r * WROW + k16 + q * 4] =
                                *(const float4*)(hp + k16 + q * 4);
                    }
                    __syncthreads();
                    const float* W = seg ? w1 : w0;
#pragma unroll 4
                    for (int k = 0; k < 256; k += 4) {
                        float4 xv = *(const float4*)&xs[bl * WROW + k];
#pragma unroll
                        for (int g = 0; g < 4; g++) {
                            float4 wv = *(const float4*)&W[(g * 16 + cl) * WROW + k];
                            a[g] = fmaf(xv.x,wv.x,fmaf(xv.y,wv.y,fmaf(xv.z,wv.z,fmaf(xv.w,wv.w,a[g]))));
                        }
                    }
                    __syncthreads();
                }
                float cn = sigm(a[1]+g_bs2[256+c]) * c_reg + sigm(a[0]+g_bs2[c]) * tanhf(a[2]+g_bs2[512+c]);
                float hn = sigm(a[3]+g_bs2[768+c]) * tanhf(cn);
                c_reg = cn;
                g_h2[(size_t)(t & 1) * BH + b * HID + c] = hn;
                if (t == VSTEP - 1) g_c2[b * HID + c] = cn;
            }
        }
    }
}

// decode cell: gates = emb[tok]@wih[:, :256]^T + h@whh^T + xgd[t]
__global__ __launch_bounds__(256) void k_dec_cell(
    const float* __restrict__ emb, const float* __restrict__ wih,
    const float* __restrict__ whh, const float* __restrict__ xgd,
    const float* __restrict__ h_in, float* __restrict__ h_out, float* __restrict__ c_st,
    float* __restrict__ caption, int t)
{
    __shared__ float xs[16][68];
    __shared__ float ws[4][16][68];
    __shared__ int stok[16];
    int tid = threadIdx.x, bl = tid & 15, cl = tid >> 4;
    int ct = blockIdx.x, bt = blockIdx.y;
    int b = bt * 16 + bl, c = ct * 16 + cl;
    const unsigned long long* gprev = g_gmax[(t ^ 1) & 1];
    if (tid < 16) stok[tid] = (t == 0) ? 0 : dec_tok(gprev[bt * 16 + tid]);
    if (ct == 0 && bt == 0 && tid < BATCH) {
        if (t > 0 && caption) caption[tid * DEC + (t - 1)] = (float)dec_tok(gprev[tid]);
        g_gmax[t & 1][tid] = 0ull;
    }
    __syncthreads();
    float a0=0.f,a1=0.f,a2=0.f,a3=0.f;
    for (int seg = 0; seg < 2; seg++) {
        for (int k0 = 0; k0 < HID; k0 += 64) {
            { int r = tid >> 4, kq = (tid & 15) << 2;
              const float* src = (seg==0) ? emb + (size_t)stok[r]*HID
                                          : h_in + (bt*16+r)*HID;
              *(float4*)&xs[r][kq] = *(const float4*)(src + k0 + kq); }
#pragma unroll
            for (int i = 0; i < 4; i++) {
                int idx = tid + i*256, r = idx >> 4, kq = (idx & 15) << 2;
                int gg = r >> 4, cr = r & 15;
                const float* wr = (seg==0) ? wih + (size_t)(gg*HID + ct*16 + cr)*512
                                           : whh + (size_t)(gg*HID + ct*16 + cr)*HID;
                *(float4*)&ws[gg][cr][kq] = *(const float4*)(wr + k0 + kq);
            }
            __syncthreads();
#pragma unroll 8
            for (int k4 = 0; k4 < 64; k4 += 4) {
                float4 xv = *(const float4*)&xs[bl][k4];
                float4 w0 = *(const float4*)&ws[0][cl][k4];
                float4 w1 = *(const float4*)&ws[1][cl][k4];
                float4 w2v= *(const float4*)&ws[2][cl][k4];
                float4 w3 = *(const float4*)&ws[3][cl][k4];
                a0=fmaf(xv.x,w0.x,fmaf(xv.y,w0.y,fmaf(xv.z,w0.z,fmaf(xv.w,w0.w,a0))));
                a1=fmaf(xv.x,w1.x,fmaf(xv.y,w1.y,fmaf(xv.z,w1.z,fmaf(xv.w,w1.w,a1))));
                a2=fmaf(xv.x,w2v.x,fmaf(xv.y,w2v.y,fmaf(xv.z,w2v.z,fmaf(xv.w,w2v.w,a2))));
                a3=fmaf(xv.x,w3.x,fmaf(xv.y,w3.y,fmaf(xv.z,w3.z,fmaf(xv.w,w3.w,a3))));
            }
            __syncthreads();
        }
    }
    const float* xr = xgd + ((size_t)t * BATCH + b) * 1024;
    float cn = sigm(a1 + xr[256+c]) * c_st[b*HID+c] + sigm(a0 + xr[c]) * tanhf(a2 + xr[512+c]);
    float hn = sigm(a3 + xr[768+c]) * tanhf(cn);
    c_st[b*HID+c] = cn;
    h_out[b*HID+c] = hn;
}

// logits: 143 blocks x 224 n-cols (full 148-SM spread), exact fp32
__global__ __launch_bounds__(512) void k_logits(
    const float* __restrict__ h, const float* __restrict__ w2, const float* __restrict__ b2,
    float* __restrict__ prob, int t, int par)
{
    __shared__ float hs[64][36];
    __shared__ float ws[32 * WPAD];
    int tid = threadIdx.x, tn = tid & 31, tw = tid >> 5;
    int b0 = tw * 4, nb = blockIdx.x * NPB;
    float acc[4][7];
#pragma unroll
    for (int i = 0; i < 4; i++)
#pragma unroll
        for (int j = 0; j < 7; j++) acc[i][j] = 0.f;

    for (int k0 = 0; k0 < HID; k0 += 32) {
        {
            int r = tid >> 3, kq = (tid & 7) << 2;
            *(float4*)&hs[r][kq] = *(const float4*)(h + r * HID + k0 + kq);
        }
#pragma unroll
        for (int i = 0; i < 4; i++) {
            int idx = tid + i * 512;
            if (idx < NPB * 8) {
                int r = idx >> 3, kq = (idx & 7) << 2;
                int n = nb + r;
                float4 v = (n < VOCAB) ? *(const float4*)(w2 + (size_t)n * HID + k0 + kq)
                                       : make_float4(0.f, 0.f, 0.f, 0.f);
                ws[(kq + 0) * WPAD + r] = v.x; ws[(kq + 1) * WPAD + r] = v.y;
                ws[(kq + 2) * WPAD + r] = v.z; ws[(kq + 3) * WPAD + r] = v.w;
            }
        }
        __syncthreads();
#pragma unroll 4
        for (int k = 0; k < 32; k++) {
            float wv[7];
#pragma unroll
            for (int j = 0; j < 7; j++) wv[j] = ws[k * WPAD + tn + 32 * j];
#pragma unroll
            for (int i = 0; i < 4; i++) {
                float hv = hs[b0 + i][k];
#pragma unroll
                for (int j = 0; j < 7; j++) acc[i][j] = fmaf(hv, wv[j], acc[i][j]);
            }
        }
        __syncthreads();
    }
    float b2v[7];
#pragma unroll
    for (int j = 0; j < 7; j++) {
        int n = nb + tn + 32 * j;
        b2v[j] = (n < VOCAB) ? b2[n] : 0.f;
    }
    unsigned long long pk[4];
#pragma unroll
    for (int i = 0; i < 4; i++) {
        int b = b0 + i;
        float* row = prob + ((size_t)b * DEC + t) * VOCAB + nb;
        float vb = -1e30f; int ni = -1;
#pragma unroll
        for (int j = 0; j < 7; j++) {
            int n = tn + 32 * j;
            if (nb + n < VOCAB) {
                float v = acc[i][j] + b2v[j];
                row[n] = v;
                if (v > vb) { vb = v; ni = n; }
            }
        }
        pk[i] = (ni >= 0) ? (((unsigned long long)f2ord(vb) << 32) |
                            (unsigned long long)(0xFFFFFFFFu - (unsigned)(nb + ni)))
                          : 0ull;
    }
#pragma unroll
    for (int off = 16; off; off >>= 1)
#pragma unroll
        for (int i = 0; i < 4; i++)
            pk[i] = pkmax(pk[i], __shfl_xor_sync(0xFFFFFFFFu, pk[i], off));
    if (tn == 0)
#pragma unroll
        for (int i = 0; i < 4; i++) atomicMax(&g_gmax[par][b0 + i], pk[i]);
}

__global__ void k_final(float* cap) {
    int b = threadIdx.x;
    if (cap && b < BATCH) cap[b * DEC + DEC - 1] = (float)dec_tok(g_gmax[(DEC - 1) & 1][b]);
}

extern "C" void kernel_launch(void* const* d_in, const int* in_sizes, int n_in,
                              void* d_out, int out_size) {
    const float* video  = (const float*)d_in[0];
    const float* w1     = (const float*)d_in[1];
    const float* b1     = (const float*)d_in[2];
    const float* w2     = (const float*)d_in[3];
    const float* b2     = (const float*)d_in[4];
    const float* l1_wih = (const float*)d_in[5];
    const float* l1_whh = (const float*)d_in[6];
    const float* l1_bih = (const float*)d_in[7];
    const float* l1_bhh = (const float*)d_in[8];
    const float* l2_wih = (const float*)d_in[9];
    const float* l2_whh = (const float*)d_in[10];
    const float* l2_bih = (const float*)d_in[11];
    const float* l2_bhh = (const float*)d_in[12];
    const float* emb    = (const float*)d_in[13];

    float *pv,*pxg1,*pxgd,*pvid,*pc2,*ph2,*pbs1,*pbs2;
    cudaGetSymbolAddress((void**)&pv,   g_v);
    cudaGetSymbolAddress((void**)&pxg1, g_xg1);
    cudaGetSymbolAddress((void**)&pxgd, g_xg2);
    cudaGetSymbolAddress((void**)&pvid, g_vid);
    cudaGetSymbolAddress((void**)&pc2,  g_c2);
    cudaGetSymbolAddress((void**)&ph2,  g_h2);
    cudaGetSymbolAddress((void**)&pbs1, g_bs1);
    cudaGetSymbolAddress((void**)&pbs2, g_bs2);

    float* cap = nullptr;
    float* prob = (float*)d_out;
    long long need = (long long)BATCH*DEC + (long long)BATCH*DEC*VOCAB;
    if ((long long)out_size >= need) { cap = (float*)d_out; prob = (float*)d_out + BATCH*DEC; }

    static int attr_set = 0;
    const int ENC_SMEM = (2 * 4 * 16 * WROW + 16 * WROW) * 4;
    if (!attr_set) {
        cudaFuncSetAttribute(k_enc, cudaFuncAttributeMaxDynamicSharedMemorySize, ENC_SMEM);
        attr_set = 1;
    }

    k_zero<<<64, 256>>>();
    k_bias<<<4, 256>>>(l1_bih, l1_bhh, l2_bih, l2_bhh);

    // v[t,b,:] = video @ w1^T + b1  (t-major), pipelined 64x64 tiles
    k_gemm64<<<dim3(80, 4), 256>>>(video, FRAME, w1, FRAME, b1, pv, HID, FRAME, VSTEP);
    // xg1 = v @ l1_wih^T + bs1
    k_gemm<<<dim3(40, 16), 256>>>(pv, HID, l1_wih, HID, 0, pbs1, pxg1, 4*HID, HID, 0);

    // fused persistent LSTM1 + LSTM2 encoder
    k_enc<<<NBLK_ENC, 256, ENC_SMEM>>>(l1_whh, l2_wih, l2_whh);

    // xgd = vid_out[80:129] @ l2_wih[:,256:]^T + bs2
    k_gemm<<<dim3(25, 16), 256>>>(pvid + (size_t)VSTEP*BH, HID, l2_wih, 2*HID, HID,
                                  pbs2, pxgd, 4*HID, HID, 0);

    // autoregressive decode
    for (int t = 0; t < DEC; t++) {
        const float* hin = ph2 + ((t + 1) & 1) * BH;
        float* hout = ph2 + (t & 1) * BH;
        k_dec_cell<<<dim3(16, 4), 256>>>(emb, l2_wih, l2_whh, pxgd, hin, hout, pc2, cap, t);
        k_logits<<<NBLK_LOG, 512>>>(hout, w2, b2, prob, t, t & 1);
    }
    k_final<<<1, 64>>>(cap);
}

// round 17
// speedup vs baseline: 1.1697x; 1.0304x over previous
#include <cuda_runtime.h>
#include <math.h>

#define VOCAB 32000
#define BATCH 64
#define FRAME 4096
#define HID 256
#define VSTEP 80
#define CSTEP 50
#define TSTEPS (VSTEP + CSTEP - 1)
#define DEC (CSTEP - 1)
#define BH (BATCH * HID)
#define NBLK_ENC 128
#define ENC_ITERS 130
#define NPB 224                 /* logits n-cols per block */
#define NBLK_LOG 144            /* 144*224 = 32256 >= 32000 */
#define WPAD 225
#define HSP 260
#define LOG_SMEM ((64 * HSP + 2 * 32 * WPAD) * 4)

__device__ float g_v  [VSTEP * BATCH * HID];
__device__ float g_xg1[VSTEP * BATCH * 4 * HID];
__device__ float g_xg2[VSTEP * BATCH * 4 * HID];   // reused as xgd
__device__ float g_vid[(TSTEPS + 1) * BATCH * HID];
__device__ float g_c2 [BH];
__device__ float g_h2 [2 * BH];
__device__ float g_bs1[4 * HID];
__device__ float g_bs2[4 * HID];
__device__ unsigned long long g_gmax[2][BATCH];
__device__ int g_bar_sense;
__device__ unsigned g_bar_count;

__device__ __forceinline__ unsigned f2ord(float f) {
    unsigned u = __float_as_uint(f);
    return (u & 0x80000000u) ? ~u : (u | 0x80000000u);
}
__device__ __forceinline__ float sigm(float x) { return 1.f / (1.f + expf(-x)); }
__device__ __forceinline__ int dec_tok(unsigned long long p) {
    return (int)(0xFFFFFFFFu - (unsigned)(p & 0xFFFFFFFFull));
}
__device__ __forceinline__ unsigned long long pkmax(unsigned long long a, unsigned long long b) {
    return a > b ? a : b;
}

__global__ void k_zero() {
    int i = blockIdx.x * blockDim.x + threadIdx.x;
    if (i < BH) { g_h2[i] = 0.f; g_h2[BH + i] = 0.f; }
}
__global__ void k_bias(const float* a1, const float* b1, const float* a2, const float* b2) {
    int i = blockIdx.x * 256 + threadIdx.x;
    if (i < 4 * HID) { g_bs1[i] = a1[i] + b1[i]; g_bs2[i] = a2[i] + b2[i]; }
}

// 128x64 tile GEMM (K=256 hoists)
__global__ __launch_bounds__(256) void k_gemm(
    const float* __restrict__ A, int lda,
    const float* __restrict__ W, int ldw, int wcol,
    const float* __restrict__ bias,
    float* __restrict__ C, int ldc, int K, int permT)
{
    __shared__ float As[16][132];
    __shared__ float Bs[16][68];
    int tid = threadIdx.x, tx = tid & 15, ty = tid >> 4;
    int m0 = blockIdx.x * 128, n0 = blockIdx.y * 64;
    float4 acc[8];
#pragma unroll
    for (int i = 0; i < 8; i++) acc[i] = make_float4(0.f,0.f,0.f,0.f);
    for (int k0 = 0; k0 < K; k0 += 16) {
#pragma unroll
        for (int i = 0; i < 2; i++) {
            int idx = tid + i * 256, r = idx >> 2, kq = (idx & 3) << 2;
            float4 va = *(const float4*)(A + (size_t)(m0 + r) * lda + k0 + kq);
            As[kq][r]=va.x; As[kq+1][r]=va.y; As[kq+2][r]=va.z; As[kq+3][r]=va.w;
        }
        {
            int r = tid >> 2, kq = (tid & 3) << 2;
            float4 vb = *(const float4*)(W + (size_t)(n0 + r) * ldw + wcol + k0 + kq);
            Bs[kq][r]=vb.x; Bs[kq+1][r]=vb.y; Bs[kq+2][r]=vb.z; Bs[kq+3][r]=vb.w;
        }
        __syncthreads();
#pragma unroll
        for (int k = 0; k < 16; k++) {
            float4 b4 = *(const float4*)&Bs[k][tx * 4];
            float4 a0 = *(const float4*)&As[k][ty * 8];
            float4 a1 = *(const float4*)&As[k][ty * 8 + 4];
            float av[8] = {a0.x,a0.y,a0.z,a0.w,a1.x,a1.y,a1.z,a1.w};
#pragma unroll
            for (int i = 0; i < 8; i++) {
                acc[i].x = fmaf(av[i], b4.x, acc[i].x);
                acc[i].y = fmaf(av[i], b4.y, acc[i].y);
                acc[i].z = fmaf(av[i], b4.z, acc[i].z);
                acc[i].w = fmaf(av[i], b4.w, acc[i].w);
            }
        }
        __syncthreads();
    }
    float4 bb = *(const float4*)(bias + n0 + tx * 4);
#pragma unroll
    for (int i = 0; i < 8; i++) {
        int m = m0 + ty * 8 + i;
        int orow = permT ? ((m % permT) * BATCH + m / permT) : m;
        *(float4*)(C + (size_t)orow * ldc + n0 + tx * 4) =
            make_float4(acc[i].x+bb.x, acc[i].y+bb.y, acc[i].z+bb.z, acc[i].w+bb.w);
    }
}

// 64x64 tile GEMM, software-pipelined (reg prefetch + double-buffered smem)
__global__ __launch_bounds__(256) void k_gemm64(
    const float* __restrict__ A, int lda,
    const float* __restrict__ W, int ldw,
    const float* __restrict__ bias,
    float* __restrict__ C, int ldc, int K, int permT)
{
    __shared__ float As[2][16][68];
    __shared__ float Bs[2][16][68];
    int tid = threadIdx.x, tx = tid & 15, ty = tid >> 4;
    int m0 = blockIdx.x * 64, n0 = blockIdx.y * 64;
    int r = tid >> 2, kq = (tid & 3) << 2;
    const float* Ap = A + (size_t)(m0 + r) * lda + kq;
    const float* Wp = W + (size_t)(n0 + r) * ldw + kq;
    int nchunk = K >> 4;

    float4 ra = *(const float4*)Ap;
    float4 rb = *(const float4*)Wp;
    As[0][kq][r]=ra.x; As[0][kq+1][r]=ra.y; As[0][kq+2][r]=ra.z; As[0][kq+3][r]=ra.w;
    Bs[0][kq][r]=rb.x; Bs[0][kq+1][r]=rb.y; Bs[0][kq+2][r]=rb.z; Bs[0][kq+3][r]=rb.w;
    __syncthreads();

    float4 acc[4];
#pragma unroll
    for (int i = 0; i < 4; i++) acc[i] = make_float4(0.f,0.f,0.f,0.f);

    for (int kc = 0; kc < nchunk; kc++) {
        int buf = kc & 1;
        if (kc + 1 < nchunk) {
            ra = *(const float4*)(Ap + (kc + 1) * 16);
            rb = *(const float4*)(Wp + (kc + 1) * 16);
        }
#pragma unroll
        for (int k = 0; k < 16; k++) {
            float4 b4 = *(const float4*)&Bs[buf][k][tx * 4];
            float4 a4 = *(const float4*)&As[buf][k][ty * 4];
            float av[4] = {a4.x, a4.y, a4.z, a4.w};
#pragma unroll
            for (int i = 0; i < 4; i++) {
                acc[i].x = fmaf(av[i], b4.x, acc[i].x);
                acc[i].y = fmaf(av[i], b4.y, acc[i].y);
                acc[i].z = fmaf(av[i], b4.z, acc[i].z);
                acc[i].w = fmaf(av[i], b4.w, acc[i].w);
            }
        }
        if (kc + 1 < nchunk) {
            int nb = buf ^ 1;
            As[nb][kq][r]=ra.x; As[nb][kq+1][r]=ra.y; As[nb][kq+2][r]=ra.z; As[nb][kq+3][r]=ra.w;
            Bs[nb][kq][r]=rb.x; Bs[nb][kq+1][r]=rb.y; Bs[nb][kq+2][r]=rb.z; Bs[nb][kq+3][r]=rb.w;
            __syncthreads();
        }
    }
    float4 bb = *(const float4*)(bias + n0 + tx * 4);
#pragma unroll
    for (int i = 0; i < 4; i++) {
        int m = m0 + ty * 4 + i;
        int orow = permT ? ((m % permT) * BATCH + m / permT) : m;
        *(float4*)(C + (size_t)orow * ldc + n0 + tx * 4) =
            make_float4(acc[i].x+bb.x, acc[i].y+bb.y, acc[i].z+bb.z, acc[i].w+bb.w);
    }
}

// ---- persistent fused encoder: blocks 0..63 = LSTM1, 64..127 = LSTM2-enc ----
#define WROW 260
__global__ __launch_bounds__(256) void k_enc(
    const float* __restrict__ l1_whh, const float* __restrict__ l2_wih,
    const float* __restrict__ l2_whh)
{
    extern __shared__ float sm[];
    float* w0 = sm;
    float* w1 = sm + 4 * 16 * WROW;
    float* xs = sm + 2 * 4 * 16 * WROW;

    int tid = threadIdx.x, bl = tid & 15, cl = tid >> 4;
    int bid = blockIdx.x;
    int role = bid >> 6;
    int lb = bid & 63, ct = lb & 15, bt = lb >> 4;
    int b = bt * 16 + bl, c = ct * 16 + cl;

    for (int i = tid; i < 4096; i += 256) {
        int row = i >> 6, kq = (i & 63) << 2;
        int g = row >> 4, cr = row & 15;
        int wrow = g * 256 + ct * 16 + cr;
        float* dst = w0 + (g * 16 + cr) * WROW + kq;
        if (role == 0) {
            float4 v = *(const float4*)(l1_whh + (size_t)wrow * 256 + kq);
            dst[0]=v.x; dst[1]=v.y; dst[2]=v.z; dst[3]=v.w;
        } else {
            float4 v = *(const float4*)(l2_wih + (size_t)wrow * 512 + 256 + kq);
            dst[0]=v.x; dst[1]=v.y; dst[2]=v.z; dst[3]=v.w;
            float4 u = *(const float4*)(l2_whh + (size_t)wrow * 256 + kq);
            float* d2 = w1 + (g * 16 + cr) * WROW + kq;
            d2[0]=u.x; d2[1]=u.y; d2[2]=u.z; d2[3]=u.w;
        }
    }

    float c_reg = 0.f;
    int sense = 0;
    volatile int* vsense = &g_bar_sense;

    for (int s = 0; s < ENC_ITERS; s++) {
        __syncthreads();
        if (tid == 0) {
            __threadfence();
            sense ^= 1;
            unsigned old = atomicAdd(&g_bar_count, 1u);
            if (old == (unsigned)(NBLK_ENC - 1)) {
                g_bar_count = 0u;
                __threadfence();
                *vsense = sense;
            } else {
                while (*vsense != sense) __nanosleep(64);
                __threadfence();
            }
        }
        __syncthreads();

        if (role == 0) {
            if (s < TSTEPS) {
                int t = s;
                {
                    int r = tid >> 4, k16 = (tid & 15) << 4;
                    const float* hp = (t == 0) ? (const float*)0
                        : g_vid + (size_t)(t - 1) * BH + (bt * 16 + r) * HID;
#pragma unroll
                    for (int q = 0; q < 4; q++) {
                        float4 v = hp ? *(const float4*)(hp + k16 + q * 4)
                                      : make_float4(0.f,0.f,0.f,0.f);
                        *(float4*)&xs[r * WROW + k16 + q * 4] = v;
                    }
                }
                __syncthreads();
                float a[4] = {0.f,0.f,0.f,0.f};
#pragma unroll 4
                for (int k = 0; k < 256; k += 4) {
                    float4 xv = *(const float4*)&xs[bl * WROW + k];
#pragma unroll
                    for (int g = 0; g < 4; g++) {
                        float4 wv = *(const float4*)&w0[(g * 16 + cl) * WROW + k];
                        a[g] = fmaf(xv.x,wv.x,fmaf(xv.y,wv.y,fmaf(xv.z,wv.z,fmaf(xv.w,wv.w,a[g]))));
                    }
                }
                float xg[4];
                if (t < VSTEP) {
                    const float* xr = g_xg1 + ((size_t)t * BATCH + b) * 1024;
#pragma unroll
                    for (int g = 0; g < 4; g++) xg[g] = xr[g * 256 + c];
                } else {
#pragma unroll
                    for (int g = 0; g < 4; g++) xg[g] = g_bs1[g * 256 + c];
                }
                float cn = sigm(a[1]+xg[1]) * c_reg + sigm(a[0]+xg[0]) * tanhf(a[2]+xg[2]);
                float hn = sigm(a[3]+xg[3]) * tanhf(cn);
                c_reg = cn;
                g_vid[(size_t)t * BH + b * HID + c] = hn;
            }
        } else {
            if (s >= 1 && s <= VSTEP) {
                int t = s - 1;
                float a[4] = {0.f,0.f,0.f,0.f};
#pragma unroll
                for (int seg = 0; seg < 2; seg++) {
                    {
                        int r = tid >> 4, k16 = (tid & 15) << 4;
                        const float* hp = (seg == 0)
                            ? g_vid + (size_t)t * BH + (bt * 16 + r) * HID
                            : g_h2 + (size_t)((t + 1) & 1) * BH + (bt * 16 + r) * HID;
#pragma unroll
                        for (int q = 0; q < 4; q++)
                            *(float4*)&xs[r * WROW + k16 + q * 4] =
                                *(const float4*)(hp + k16 + q * 4);
                    }
                    __syncthreads();
                    const float* W = seg ? w1 : w0;
#pragma unroll 4
                    for (int k = 0; k < 256; k += 4) {
                        float4 xv = *(const float4*)&xs[bl * WROW + k];
#pragma unroll
                        for (int g = 0; g < 4; g++) {
                            float4 wv = *(const float4*)&W[(g * 16 + cl) * WROW + k];
                            a[g] = fmaf(xv.x,wv.x,fmaf(xv.y,wv.y,fmaf(xv.z,wv.z,fmaf(xv.w,wv.w,a[g]))));
                        }
                    }
                    __syncthreads();
                }
                float cn = sigm(a[1]+g_bs2[256+c]) * c_reg + sigm(a[0]+g_bs2[c]) * tanhf(a[2]+g_bs2[512+c]);
                float hn = sigm(a[3]+g_bs2[768+c]) * tanhf(cn);
                c_reg = cn;
                g_h2[(size_t)(t & 1) * BH + b * HID + c] = hn;
                if (t == VSTEP - 1) g_c2[b * HID + c] = cn;
            }
        }
    }
}

// decode cell: gates = emb[tok]@wih[:, :256]^T + h@whh^T + xgd[t]
__global__ __launch_bounds__(256) void k_dec_cell(
    const float* __restrict__ emb, const float* __restrict__ wih,
    const float* __restrict__ whh, const float* __restrict__ xgd,
    const float* __restrict__ h_in, float* __restrict__ h_out, float* __restrict__ c_st,
    float* __restrict__ caption, int t)
{
    __shared__ float xs[16][68];
    __shared__ float ws[4][16][68];
    __shared__ int stok[16];
    int tid = threadIdx.x, bl = tid & 15, cl = tid >> 4;
    int ct = blockIdx.x, bt = blockIdx.y;
    int b = bt * 16 + bl, c = ct * 16 + cl;
    const unsigned long long* gprev = g_gmax[(t ^ 1) & 1];
    if (tid < 16) stok[tid] = (t == 0) ? 0 : dec_tok(gprev[bt * 16 + tid]);
    if (ct == 0 && bt == 0 && tid < BATCH) {
        if (t > 0 && caption) caption[tid * DEC + (t - 1)] = (float)dec_tok(gprev[tid]);
        g_gmax[t & 1][tid] = 0ull;
    }
    __syncthreads();
    float a0=0.f,a1=0.f,a2=0.f,a3=0.f;
    for (int seg = 0; seg < 2; seg++) {
        for (int k0 = 0; k0 < HID; k0 += 64) {
            { int r = tid >> 4, kq = (tid & 15) << 2;
              const float* src = (seg==0) ? emb + (size_t)stok[r]*HID
                                          : h_in + (bt*16+r)*HID;
              *(float4*)&xs[r][kq] = *(const float4*)(src + k0 + kq); }
#pragma unroll
            for (int i = 0; i < 4; i++) {
                int idx = tid + i*256, r = idx >> 4, kq = (idx & 15) << 2;
                int gg = r >> 4, cr = r & 15;
                const float* wr = (seg==0) ? wih + (size_t)(gg*HID + ct*16 + cr)*512
                                           : whh + (size_t)(gg*HID + ct*16 + cr)*HID;
                *(float4*)&ws[gg][cr][kq] = *(const float4*)(wr + k0 + kq);
            }
            __syncthreads();
#pragma unroll 8
            for (int k4 = 0; k4 < 64; k4 += 4) {
                float4 xv = *(const float4*)&xs[bl][k4];
                float4 w0 = *(const float4*)&ws[0][cl][k4];
                float4 w1 = *(const float4*)&ws[1][cl][k4];
                float4 w2v= *(const float4*)&ws[2][cl][k4];
                float4 w3 = *(const float4*)&ws[3][cl][k4];
                a0=fmaf(xv.x,w0.x,fmaf(xv.y,w0.y,fmaf(xv.z,w0.z,fmaf(xv.w,w0.w,a0))));
                a1=fmaf(xv.x,w1.x,fmaf(xv.y,w1.y,fmaf(xv.z,w1.z,fmaf(xv.w,w1.w,a1))));
                a2=fmaf(xv.x,w2v.x,fmaf(xv.y,w2v.y,fmaf(xv.z,w2v.z,fmaf(xv.w,w2v.w,a2))));
                a3=fmaf(xv.x,w3.x,fmaf(xv.y,w3.y,fmaf(xv.z,w3.z,fmaf(xv.w,w3.w,a3))));
            }
            __syncthreads();
        }
    }
    const float* xr = xgd + ((size_t)t * BATCH + b) * 1024;
    float cn = sigm(a1 + xr[256+c]) * c_st[b*HID+c] + sigm(a0 + xr[c]) * tanhf(a2 + xr[512+c]);
    float hn = sigm(a3 + xr[768+c]) * tanhf(cn);
    c_st[b*HID+c] = cn;
    h_out[b*HID+c] = hn;
}

// logits: 144 blocks x 224 n-cols; hs staged once, ws double-buffered (1 sync/chunk)
__global__ __launch_bounds__(512) void k_logits(
    const float* __restrict__ h, const float* __restrict__ w2, const float* __restrict__ b2,
    float* __restrict__ prob, int t, int par)
{
    extern __shared__ float S[];
    float* hs = S;                 // [64][HSP]
    float* ws = S + 64 * HSP;      // [2][32*WPAD]
    int tid = threadIdx.x, tn = tid & 31, tw = tid >> 5;
    int b0 = tw * 4, nb = blockIdx.x * NPB;

    // stage all of h (64 x 256)
#pragma unroll
    for (int i = 0; i < 8; i++) {
        int idx = tid + i * 512, r = idx >> 6, kq = (idx & 63) << 2;
        *(float4*)&hs[r * HSP + kq] = *(const float4*)(h + r * HID + kq);
    }
    // stage chunk 0 of w2 into buffer 0
#pragma unroll
    for (int i = 0; i < 4; i++) {
        int idx = tid + i * 512;
        if (idx < NPB * 8) {
            int r = idx >> 3, kq = (idx & 7) << 2;
            int n = nb + r;
            float4 v = (n < VOCAB) ? *(const float4*)(w2 + (size_t)n * HID + kq)
                                   : make_float4(0.f, 0.f, 0.f, 0.f);
            ws[(kq + 0) * WPAD + r] = v.x; ws[(kq + 1) * WPAD + r] = v.y;
            ws[(kq + 2) * WPAD + r] = v.z; ws[(kq + 3) * WPAD + r] = v.w;
        }
    }
    __syncthreads();

    float acc[4][7];
#pragma unroll
    for (int i = 0; i < 4; i++)
#pragma unroll
        for (int j = 0; j < 7; j++) acc[i][j] = 0.f;

    for (int kc = 0; kc < 8; kc++) {
        const float* wsb = ws + (kc & 1) * 32 * WPAD;
        float4 pre[4];
        if (kc < 7) {
#pragma unroll
            for (int i = 0; i < 4; i++) {
                int idx = tid + i * 512;
                pre[i] = make_float4(0.f, 0.f, 0.f, 0.f);
                if (idx < NPB * 8) {
                    int r = idx >> 3, kq = (idx & 7) << 2;
                    int n = nb + r;
                    if (n < VOCAB)
                        pre[i] = *(const float4*)(w2 + (size_t)n * HID + (kc + 1) * 32 + kq);
                }
            }
        }
#pragma unroll 4
        for (int k = 0; k < 32; k++) {
            float wv[7];
#pragma unroll
            for (int j = 0; j < 7; j++) wv[j] = wsb[k * WPAD + tn + 32 * j];
#pragma unroll
            for (int i = 0; i < 4; i++) {
                float hv = hs[(b0 + i) * HSP + kc * 32 + k];
#pragma unroll
                for (int j = 0; j < 7; j++) acc[i][j] = fmaf(hv, wv[j], acc[i][j]);
            }
        }
        if (kc < 7) {
            float* wsn = ws + ((kc & 1) ^ 1) * 32 * WPAD;
#pragma unroll
            for (int i = 0; i < 4; i++) {
                int idx = tid + i * 512;
                if (idx < NPB * 8) {
                    int r = idx >> 3, kq = (idx & 7) << 2;
                    wsn[(kq + 0) * WPAD + r] = pre[i].x; wsn[(kq + 1) * WPAD + r] = pre[i].y;
                    wsn[(kq + 2) * WPAD + r] = pre[i].z; wsn[(kq + 3) * WPAD + r] = pre[i].w;
                }
            }
            __syncthreads();
        }
    }

    float b2v[7];
#pragma unroll
    for (int j = 0; j < 7; j++) {
        int n = nb + tn + 32 * j;
        b2v[j] = (n < VOCAB) ? b2[n] : 0.f;
    }
    unsigned long long pk[4];
#pragma unroll
    for (int i = 0; i < 4; i++) {
        int b = b0 + i;
        float* row = prob + ((size_t)b * DEC + t) * VOCAB + nb;
        float vb = -1e30f; int ni = -1;
#pragma unroll
        for (int j = 0; j < 7; j++) {
            int n = tn + 32 * j;
            if (nb + n < VOCAB) {
                float v = acc[i][j] + b2v[j];
                row[n] = v;
                if (v > vb) { vb = v; ni = n; }
            }
        }
        pk[i] = (ni >= 0) ? (((unsigned long long)f2ord(vb) << 32) |
                            (unsigned long long)(0xFFFFFFFFu - (unsigned)(nb + ni)))
                          : 0ull;
    }
#pragma unroll
    for (int off = 16; off; off >>= 1)
#pragma unroll
        for (int i = 0; i < 4; i++)
            pk[i] = pkmax(pk[i], __shfl_xor_sync(0xFFFFFFFFu, pk[i], off));
    if (tn == 0)
#pragma unroll
        for (int i = 0; i < 4; i++) atomicMax(&g_gmax[par][b0 + i], pk[i]);
}

__global__ void k_final(float* cap) {
    int b = threadIdx.x;
    if (cap && b < BATCH) cap[b * DEC + DEC - 1] = (float)dec_tok(g_gmax[(DEC - 1) & 1][b]);
}

extern "C" void kernel_launch(void* const* d_in, const int* in_sizes, int n_in,
                              void* d_out, int out_size) {
    const float* video  = (const float*)d_in[0];
    const float* w1     = (const float*)d_in[1];
    const float* b1     = (const float*)d_in[2];
    const float* w2     = (const float*)d_in[3];
    const float* b2     = (const float*)d_in[4];
    const float* l1_wih = (const float*)d_in[5];
    const float* l1_whh = (const float*)d_in[6];
    const float* l1_bih = (const float*)d_in[7];
    const float* l1_bhh = (const float*)d_in[8];
    const float* l2_wih = (const float*)d_in[9];
    const float* l2_whh = (const float*)d_in[10];
    const float* l2_bih = (const float*)d_in[11];
    const float* l2_bhh = (const float*)d_in[12];
    const float* emb    = (const float*)d_in[13];

    float *pv,*pxg1,*pxgd,*pvid,*pc2,*ph2,*pbs1,*pbs2;
    cudaGetSymbolAddress((void**)&pv,   g_v);
    cudaGetSymbolAddress((void**)&pxg1, g_xg1);
    cudaGetSymbolAddress((void**)&pxgd, g_xg2);
    cudaGetSymbolAddress((void**)&pvid, g_vid);
    cudaGetSymbolAddress((void**)&pc2,  g_c2);
    cudaGetSymbolAddress((void**)&ph2,  g_h2);
    cudaGetSymbolAddress((void**)&pbs1, g_bs1);
    cudaGetSymbolAddress((void**)&pbs2, g_bs2);

    float* cap = nullptr;
    float* prob = (float*)d_out;
    long long need = (long long)BATCH*DEC + (long long)BATCH*DEC*VOCAB;
    if ((long long)out_size >= need) { cap = (float*)d_out; prob = (float*)d_out + BATCH*DEC; }

    static int attr_set = 0;
    const int ENC_SMEM = (2 * 4 * 16 * WROW + 16 * WROW) * 4;
    if (!attr_set) {
        cudaFuncSetAttribute(k_enc, cudaFuncAttributeMaxDynamicSharedMemorySize, ENC_SMEM);
        cudaFuncSetAttribute(k_logits, cudaFuncAttributeMaxDynamicSharedMemorySize, LOG_SMEM);
        attr_set = 1;
    }

    k_zero<<<64, 256>>>();
    k_bias<<<4, 256>>>(l1_bih, l1_bhh, l2_bih, l2_bhh);

    // v[t,b,:] = video @ w1^T + b1  (t-major), pipelined 64x64 tiles
    k_gemm64<<<dim3(80, 4), 256>>>(video, FRAME, w1, FRAME, b1, pv, HID, FRAME, VSTEP);
    // xg1 = v @ l1_wih^T + bs1
    k_gemm<<<dim3(40, 16), 256>>>(pv, HID, l1_wih, HID, 0, pbs1, pxg1, 4*HID, HID, 0);

    // fused persistent LSTM1 + LSTM2 encoder
    k_enc<<<NBLK_ENC, 256, ENC_SMEM>>>(l1_whh, l2_wih, l2_whh);

    // xgd = vid_out[80:129] @ l2_wih[:,256:]^T + bs2
    k_gemm<<<dim3(25, 16), 256>>>(pvid + (size_t)VSTEP*BH, HID, l2_wih, 2*HID, HID,
                                  pbs2, pxgd, 4*HID, HID, 0);

    // autoregressive decode
    for (int t = 0; t < DEC; t++) {
        const float* hin = ph2 + ((t + 1) & 1) * BH;
        float* hout = ph2 + (t & 1) * BH;
        k_dec_cell<<<dim3(16, 4), 256>>>(emb, l2_wih, l2_whh, pxgd, hin, hout, pc2, cap, t);
        k_logits<<<NBLK_LOG, 512, LOG_SMEM>>>(hout, w2, b2, prob, t, t & 1);
    }
    k_final<<<1, 64>>>(cap);
}